// round 4
// baseline (speedup 1.0000x reference)
#include <cuda_runtime.h>
#include <math.h>

typedef unsigned long long ULL;

// ---------------- constants ----------------
#define B_   64
#define TT   63          // time steps actually computed (T-1)
#define EE   512
#define HH   1024
#define VV   32000
#define G4   4096        // 4*H

// ---------------- scratch (device globals; no allocation) ----------------
__device__ float g_Wih0p[G4 * EE];          //  8.4 MB  gate-interleaved W_ih0
__device__ float g_Whh0p[G4 * HH];          // 16.8 MB  gate-interleaved W_hh0
__device__ float g_W1cat[G4 * 2 * HH];      // 33.6 MB  [W_ih1 | W_hh1] interleaved
__device__ float g_b0p[G4];
__device__ float g_b1p[G4];
__device__ float g_G0x[TT * B_ * G4];       // 66 MB    x-side layer0 gates (+bias)
__device__ float g_H1 [TT * B_ * HH];       // 16.5 MB  h1 per step
__device__ float g_h0buf[2][B_ * HH];
__device__ float g_h1buf[2][B_ * HH];
__device__ float g_c0s[B_ * HH];
__device__ float g_c1s[B_ * HH];
__device__ ULL   g_keys[TT * B_];           // packed argmax keys, indexed t*64+b

// ---------------- helpers ----------------
static __device__ __forceinline__ ULL dup2(float b) {
    ULL r; unsigned u = __float_as_uint(b);
    asm("mov.b64 %0, {%1, %1};" : "=l"(r) : "r"(u));
    return r;
}
static __device__ __forceinline__ void fma2(ULL& acc, ULL a, ULL b) {
    asm("fma.rn.f32x2 %0, %1, %2, %0;" : "+l"(acc) : "l"(a), "l"(b));
}
static __device__ __forceinline__ ULL mk2(float x, float y) {
    ULL r;
    asm("mov.b64 %0, {%1, %2};" : "=l"(r)
        : "r"(__float_as_uint(x)), "r"(__float_as_uint(y)));
    return r;
}
static __device__ __forceinline__ float selh(ULL u, int hi) {
    return __uint_as_float(hi ? (unsigned)(u >> 32) : (unsigned)u);
}
static __device__ __forceinline__ float sigf(float x) { return 1.0f / (1.0f + expf(-x)); }
static __device__ __forceinline__ unsigned fordu(float v) {
    unsigned u = __float_as_uint(v);
    return u ^ (((int)u >> 31) | 0x80000000u);
}
static __device__ __forceinline__ ULL mkkey(float v, int col) {
    return ((ULL)fordu(v) << 32) | (ULL)(0xFFFFFFFFu - (unsigned)col);
}

// ---------------- 1) pack / init ----------------
__global__ void pack_kernel(const float* __restrict__ Wih0, const float* __restrict__ Whh0,
                            const float* __restrict__ Wih1, const float* __restrict__ Whh1,
                            const float* __restrict__ bih0, const float* __restrict__ bhh0,
                            const float* __restrict__ bih1, const float* __restrict__ bhh1) {
    int i = blockIdx.x * 256 + threadIdx.x;           // covers 4096*2048
    if (i < TT * B_) g_keys[i] = 0ull;
    int rp  = i >> 11;                                // new (interleaved) row
    int k   = i & 2047;
    int old = ((rp & 3) << 10) + (rp >> 2);           // gate*1024 + hidden
    g_W1cat[i] = (k < HH) ? Wih1[old * HH + k] : Whh1[old * HH + (k - HH)];
    if (k < EE) g_Wih0p[rp * EE + k] = Wih0[old * EE + k];
    if (k < HH) g_Whh0p[rp * HH + k] = Whh0[old * HH + k];
    if (k == 0) {
        g_b0p[rp] = bih0[old] + bhh0[old];
        g_b1p[rp] = bih1[old] + bhh1[old];
    }
}

// ---------------- 2) h0 = initial_state @ enc_proj_W^T  (also c0,h1,c1) ----------------
// tile 64x32, 128 threads, grid 32, K=2048  (small one-time kernel, kept simple)
__global__ __launch_bounds__(128) void h0init_kernel(const float* __restrict__ S,
                                                     const float* __restrict__ EW) {
    __shared__ float A_sm[32 * 66];
    __shared__ float B_sm[32 * 36];
    int tid = threadIdx.x, tr = tid >> 3, tc = tid & 7;
    int cb = blockIdx.x * 32;
    ULL acc[2][4] = {{0,0,0,0},{0,0,0,0}};
    float pA[16], pB[8];
    #pragma unroll
    for (int e = 0; e < 16; e++) { int idx = e*128+tid; pA[e] = S[(idx>>5)*2048 + (idx&31)]; }
    #pragma unroll
    for (int e = 0; e < 8;  e++) { int idx = e*128+tid; pB[e] = EW[(size_t)(cb+(idx>>5))*2048 + (idx&31)]; }
    for (int k0 = 0; k0 < 2048; k0 += 32) {
        __syncthreads();
        #pragma unroll
        for (int e = 0; e < 16; e++) { int idx = e*128+tid; A_sm[(idx&31)*66 + (idx>>5)] = pA[e]; }
        #pragma unroll
        for (int e = 0; e < 8;  e++) { int idx = e*128+tid; B_sm[(idx&31)*36 + (idx>>5)] = pB[e]; }
        __syncthreads();
        int kn = k0 + 32;
        if (kn < 2048) {
            #pragma unroll
            for (int e = 0; e < 16; e++) { int idx = e*128+tid; pA[e] = S[(idx>>5)*2048 + kn + (idx&31)]; }
            #pragma unroll
            for (int e = 0; e < 8;  e++) { int idx = e*128+tid; pB[e] = EW[(size_t)(cb+(idx>>5))*2048 + kn + (idx&31)]; }
        }
        #pragma unroll 8
        for (int kk = 0; kk < 32; kk++) {
            const ULL* ar = reinterpret_cast<const ULL*>(A_sm + kk * 66);
            ULL a0 = ar[2*tr], a1 = ar[2*tr+1];
            float4 bv = *reinterpret_cast<const float4*>(B_sm + kk*36 + 4*tc);
            ULL b0 = dup2(bv.x), b1 = dup2(bv.y), b2 = dup2(bv.z), b3 = dup2(bv.w);
            fma2(acc[0][0], a0, b0); fma2(acc[1][0], a1, b0);
            fma2(acc[0][1], a0, b1); fma2(acc[1][1], a1, b1);
            fma2(acc[0][2], a0, b2); fma2(acc[1][2], a1, b2);
            fma2(acc[0][3], a0, b3); fma2(acc[1][3], a1, b3);
        }
    }
    #pragma unroll
    for (int p = 0; p < 2; p++) {
        #pragma unroll
        for (int hi = 0; hi < 2; hi++) {
            int r = 4*tr + 2*p + hi;
            #pragma unroll
            for (int c = 0; c < 4; c++) {
                int col = cb + 4*tc + c;
                float v = selh(acc[p][c], hi);
                g_h0buf[0][r*HH + col] = v;
                g_c0s   [r*HH + col]   = v;
                g_h1buf[0][r*HH + col] = v;
                g_c1s   [r*HH + col]   = v;
            }
        }
    }
}

// ---------------- 3) G0x = emb[ids] @ Wih0p^T + b0p  ----------------
// tile 64x128, 256 threads (2 warps/SMSP, 2 CTAs/SM), grid (63, 32), K=512
// A duplicated pairs in smem, B natural col-pairs, swizzled smem layout.
__global__ __launch_bounds__(256, 2) void embx_kernel(const int* __restrict__ ids,
                                                      const float* __restrict__ emb) {
    __shared__ ULL   A_smd[32 * 66];
    __shared__ float B_sm [32 * 132];
    __shared__ int   ids_sm[B_];
    int tid = threadIdx.x, tr = tid >> 3, tc = tid & 7;
    int t = blockIdx.x, cb = blockIdx.y * 128;
    if (tid < B_) ids_sm[tid] = ids[tid * 64 + t];
    __syncthreads();
    ULL acc[2][8];
    #pragma unroll
    for (int r = 0; r < 2; r++)
        #pragma unroll
        for (int c = 0; c < 8; c++) acc[r][c] = 0ull;

    // precomputed per-element copy indices
    int aS[8], bS[16];                 // smem target indices
    size_t aG[8]; int bR[16], bK[16];  // global offsets
    #pragma unroll
    for (int e = 0; e < 8; e++) {
        int idx = e*256+tid; int k = idx&31, row = idx>>5;
        aS[e] = k*66 + (((row>>1) ^ (k>>3)) << 1) + (row&1);
        aG[e] = (size_t)ids_sm[row] * EE + k;
    }
    #pragma unroll
    for (int e = 0; e < 16; e++) {
        int idx = e*256+tid; int k = idx&31, c = idx>>5;
        bS[e] = k*132 + (((c>>2) ^ (k>>3)) << 2) + (c&3);
        bR[e] = cb + c; bK[e] = k;
    }

    float pA[8], pB[16];
    #pragma unroll
    for (int e = 0; e < 8;  e++) pA[e] = emb[aG[e]];
    #pragma unroll
    for (int e = 0; e < 16; e++) pB[e] = g_Wih0p[(size_t)bR[e]*EE + bK[e]];

    for (int k0 = 0; k0 < EE; k0 += 32) {
        __syncthreads();
        #pragma unroll
        for (int e = 0; e < 8;  e++) A_smd[aS[e]] = dup2(pA[e]);
        #pragma unroll
        for (int e = 0; e < 16; e++) B_sm[bS[e]]  = pB[e];
        __syncthreads();
        int kn = k0 + 32;
        if (kn < EE) {
            #pragma unroll
            for (int e = 0; e < 8;  e++) pA[e] = emb[aG[e] + kn];
            #pragma unroll
            for (int e = 0; e < 16; e++) pB[e] = g_Wih0p[(size_t)bR[e]*EE + kn + bK[e]];
        }
        #pragma unroll
        for (int sb = 0; sb < 4; sb++) {
            const ULL*   pa = A_smd + ((tr ^ sb) << 1);
            const float* pb = B_sm  + ((tc ^ sb) << 2);
            #pragma unroll
            for (int k2 = 0; k2 < 8; k2++) {
                int kk = sb*8 + k2;
                ulonglong2 av = *reinterpret_cast<const ulonglong2*>(pa + kk*66);
                #pragma unroll
                for (int jj = 0; jj < 4; jj++) {
                    ulonglong2 bv = *reinterpret_cast<const ulonglong2*>(pb + kk*132 + 32*jj);
                    fma2(acc[0][2*jj],   av.x, bv.x); fma2(acc[0][2*jj+1], av.x, bv.y);
                    fma2(acc[1][2*jj],   av.y, bv.x); fma2(acc[1][2*jj+1], av.y, bv.y);
                }
            }
        }
    }
    float* outp = g_G0x + (size_t)(t * B_) * G4;
    #pragma unroll
    for (int jj = 0; jj < 4; jj++) {
        int col0 = cb + 4*tc + 32*jj;
        float4 bb = *reinterpret_cast<const float4*>(g_b0p + col0);
        #pragma unroll
        for (int r = 0; r < 2; r++) {
            int row = 2*tr + r;
            float4 v;
            v.x = selh(acc[r][2*jj],0)   + bb.x;
            v.y = selh(acc[r][2*jj],1)   + bb.y;
            v.z = selh(acc[r][2*jj+1],0) + bb.z;
            v.w = selh(acc[r][2*jj+1],1) + bb.w;
            *reinterpret_cast<float4*>(outp + (size_t)row*G4 + col0) = v;
        }
    }
}

// ---------------- 4) fused LSTM cell step (one layer) ----------------
// tile 64x32 gate-cols, 256 threads (2 warps/SMSP), grid 128, smem double-buffered
__global__ __launch_bounds__(256) void cell_kernel(int t, int layer) {
    __shared__ ULL   Abuf[2][32 * 66];
    __shared__ float Bbuf[2][32 * 36];
    int tid = threadIdx.x;
    int tr = tid >> 3;      // row pair 0..31
    int tc = tid & 7;       // 4 gate cols
    int cb = blockIdx.x * 32;
    int in = t & 1, out = in ^ 1;

    const float *A1, *A2, *W;
    float *cst, *hout, *hcopy = nullptr;
    int K;
    if (layer == 0) {
        A1 = g_h0buf[in]; A2 = A1; W = g_Whh0p; K = HH;
        cst = g_c0s; hout = g_h0buf[out];
    } else {
        A1 = g_h0buf[out]; A2 = g_h1buf[in]; W = g_W1cat; K = 2 * HH;
        cst = g_c1s; hout = g_h1buf[out];
        hcopy = g_H1 + (size_t)(t * B_) * HH;
    }

    int gc0 = cb + 4 * tc;
    ULL acc[2][2];
    if (layer == 0) {
        const float* initp = g_G0x + (size_t)(t * B_) * G4;
        float4 i0 = *reinterpret_cast<const float4*>(initp + (size_t)(2*tr)   * G4 + gc0);
        float4 i1 = *reinterpret_cast<const float4*>(initp + (size_t)(2*tr+1) * G4 + gc0);
        acc[0][0] = mk2(i0.x, i0.y); acc[0][1] = mk2(i0.z, i0.w);
        acc[1][0] = mk2(i1.x, i1.y); acc[1][1] = mk2(i1.z, i1.w);
    } else {
        float4 bb = *reinterpret_cast<const float4*>(g_b1p + gc0);
        acc[0][0] = mk2(bb.x, bb.y); acc[1][0] = acc[0][0];
        acc[0][1] = mk2(bb.z, bb.w); acc[1][1] = acc[0][1];
    }

    // precomputed copy indices
    int aS[8], aR[8], aK[8], bS[4]; size_t bG[4];
    #pragma unroll
    for (int e = 0; e < 8; e++) {
        int idx = e*256+tid; int k = idx&31, row = idx>>5;
        aS[e] = k*66 + (((row>>1) ^ (k>>3)) << 1) + (row&1);
        aR[e] = row * HH; aK[e] = k;
    }
    #pragma unroll
    for (int e = 0; e < 4; e++) {
        int idx = e*256+tid; int k = idx&31, c = idx>>5;
        bS[e] = k*36 + (((c>>2) ^ (k>>3)) << 2) + (c&3);
        bG[e] = (size_t)(cb + c) * K + k;
    }

    int nb = K >> 5;
    float pA[8], pB[4];
    // load + store block 0
    #pragma unroll
    for (int e = 0; e < 8; e++) pA[e] = A1[aR[e] + aK[e]];
    #pragma unroll
    for (int e = 0; e < 4; e++) pB[e] = W[bG[e]];
    #pragma unroll
    for (int e = 0; e < 8; e++) Abuf[0][aS[e]] = dup2(pA[e]);
    #pragma unroll
    for (int e = 0; e < 4; e++) Bbuf[0][bS[e]] = pB[e];
    // load block 1
    {
        const float* Asrc = (32 < HH) ? (A1 + 32) : (A2 + (32 - HH));
        #pragma unroll
        for (int e = 0; e < 8; e++) pA[e] = Asrc[aR[e] + aK[e]];
        #pragma unroll
        for (int e = 0; e < 4; e++) pB[e] = W[bG[e] + 32];
    }

    for (int blk = 0; blk < nb; blk++) {
        __syncthreads();
        int cur = blk & 1, nxt = cur ^ 1;
        if (blk + 1 < nb) {
            #pragma unroll
            for (int e = 0; e < 8; e++) Abuf[nxt][aS[e]] = dup2(pA[e]);
            #pragma unroll
            for (int e = 0; e < 4; e++) Bbuf[nxt][bS[e]] = pB[e];
            if (blk + 2 < nb) {
                int k0 = (blk + 2) << 5;
                const float* Asrc = (k0 < HH) ? (A1 + k0) : (A2 + (k0 - HH));
                #pragma unroll
                for (int e = 0; e < 8; e++) pA[e] = Asrc[aR[e] + aK[e]];
                #pragma unroll
                for (int e = 0; e < 4; e++) pB[e] = W[bG[e] + k0];
            }
        }
        const ULL*   Ab = Abuf[cur];
        const float* Bb = Bbuf[cur];
        #pragma unroll
        for (int sb = 0; sb < 4; sb++) {
            const ULL*   pa = Ab + ((tr ^ sb) << 1);
            const float* pb = Bb + ((tc ^ sb) << 2);
            #pragma unroll
            for (int k2 = 0; k2 < 8; k2++) {
                int kk = sb*8 + k2;
                ulonglong2 av = *reinterpret_cast<const ulonglong2*>(pa + kk*66);
                ulonglong2 bv = *reinterpret_cast<const ulonglong2*>(pb + kk*36);
                fma2(acc[0][0], av.x, bv.x); fma2(acc[0][1], av.x, bv.y);
                fma2(acc[1][0], av.y, bv.x); fma2(acc[1][1], av.y, bv.y);
            }
        }
    }

    // fused LSTM activation epilogue (thread owns gates i,f,g,o of hidden j)
    int j = (cb >> 2) + tc;
    #pragma unroll
    for (int r = 0; r < 2; r++) {
        int row = 2*tr + r;
        float iv = selh(acc[r][0], 0);
        float fv = selh(acc[r][0], 1);
        float gv = selh(acc[r][1], 0);
        float ov = selh(acc[r][1], 1);
        float cold = cst[row*HH + j];
        float cn = sigf(fv) * cold + sigf(iv) * tanhf(gv);
        float h  = sigf(ov) * tanhf(cn);
        cst [row*HH + j] = cn;
        hout[row*HH + j] = h;
        if (hcopy) hcopy[row*HH + j] = h;
    }
}

// ---------------- 5) logits = H1 @ proj_W^T + b, fused argmax ----------------
// tile 64x128, 256 threads, 2 CTAs/SM, grid (63, 250), K=1024
__global__ __launch_bounds__(256, 2) void proj_kernel(const float* __restrict__ PW,
                                                      const float* __restrict__ PB,
                                                      float* __restrict__ out) {
    __shared__ ULL   A_smd[32 * 66];
    __shared__ float B_sm [32 * 132];
    int tid = threadIdx.x, tr = tid >> 3, tc = tid & 7;
    int t = blockIdx.x, cb = blockIdx.y * 128;
    const float* A = g_H1 + (size_t)(t * B_) * HH;
    ULL acc[2][8];
    #pragma unroll
    for (int r = 0; r < 2; r++)
        #pragma unroll
        for (int c = 0; c < 8; c++) acc[r][c] = 0ull;

    int aS[8], aR[8], aK[8], bS[16]; size_t bG[16];
    #pragma unroll
    for (int e = 0; e < 8; e++) {
        int idx = e*256+tid; int k = idx&31, row = idx>>5;
        aS[e] = k*66 + (((row>>1) ^ (k>>3)) << 1) + (row&1);
        aR[e] = row * HH; aK[e] = k;
    }
    #pragma unroll
    for (int e = 0; e < 16; e++) {
        int idx = e*256+tid; int k = idx&31, c = idx>>5;
        bS[e] = k*132 + (((c>>2) ^ (k>>3)) << 2) + (c&3);
        bG[e] = (size_t)(cb + c) * HH + k;
    }

    float pA[8], pB[16];
    #pragma unroll
    for (int e = 0; e < 8;  e++) pA[e] = A[aR[e] + aK[e]];
    #pragma unroll
    for (int e = 0; e < 16; e++) pB[e] = PW[bG[e]];

    for (int k0 = 0; k0 < HH; k0 += 32) {
        __syncthreads();
        #pragma unroll
        for (int e = 0; e < 8;  e++) A_smd[aS[e]] = dup2(pA[e]);
        #pragma unroll
        for (int e = 0; e < 16; e++) B_sm[bS[e]]  = pB[e];
        __syncthreads();
        int kn = k0 + 32;
        if (kn < HH) {
            #pragma unroll
            for (int e = 0; e < 8;  e++) pA[e] = A[aR[e] + kn + aK[e]];
            #pragma unroll
            for (int e = 0; e < 16; e++) pB[e] = PW[bG[e] + kn];
        }
        #pragma unroll
        for (int sb = 0; sb < 4; sb++) {
            const ULL*   pa = A_smd + ((tr ^ sb) << 1);
            const float* pb = B_sm  + ((tc ^ sb) << 2);
            #pragma unroll
            for (int k2 = 0; k2 < 8; k2++) {
                int kk = sb*8 + k2;
                ulonglong2 av = *reinterpret_cast<const ulonglong2*>(pa + kk*66);
                #pragma unroll
                for (int jj = 0; jj < 4; jj++) {
                    ulonglong2 bv = *reinterpret_cast<const ulonglong2*>(pb + kk*132 + 32*jj);
                    fma2(acc[0][2*jj],   av.x, bv.x); fma2(acc[0][2*jj+1], av.x, bv.y);
                    fma2(acc[1][2*jj],   av.y, bv.x); fma2(acc[1][2*jj+1], av.y, bv.y);
                }
            }
        }
    }

    float* lout = out + TT * B_;                 // logits after preds
    ULL rowkey[2] = {0ull, 0ull};
    #pragma unroll
    for (int jj = 0; jj < 4; jj++) {
        int col0 = cb + 4*tc + 32*jj;
        float4 bb = *reinterpret_cast<const float4*>(PB + col0);
        #pragma unroll
        for (int r = 0; r < 2; r++) {
            int b = 2*tr + r;
            float4 v;
            v.x = selh(acc[r][2*jj],0)   + bb.x;
            v.y = selh(acc[r][2*jj],1)   + bb.y;
            v.z = selh(acc[r][2*jj+1],0) + bb.z;
            v.w = selh(acc[r][2*jj+1],1) + bb.w;
            *reinterpret_cast<float4*>(lout + ((size_t)b * TT + t) * VV + col0) = v;
            ULL key = mkkey(v.x, col0);
            ULL k2  = mkkey(v.y, col0 + 1); if (k2 > key) key = k2;
            k2      = mkkey(v.z, col0 + 2); if (k2 > key) key = k2;
            k2      = mkkey(v.w, col0 + 3); if (k2 > key) key = k2;
            if (key > rowkey[r]) rowkey[r] = key;
        }
    }
    #pragma unroll
    for (int r = 0; r < 2; r++) {
        ULL key = rowkey[r];
        #pragma unroll
        for (int off = 4; off > 0; off >>= 1) {   // reduce across tc lanes (bits 0..2)
            ULL o = __shfl_xor_sync(0xFFFFFFFFu, key, off);
            if (o > key) key = o;
        }
        if (tc == 0) atomicMax(&g_keys[t * B_ + (2*tr + r)], key);
    }
}

// ---------------- 6) finalize preds ----------------
__global__ void preds_kernel(float* __restrict__ out) {
    int i = blockIdx.x * 256 + threadIdx.x;
    if (i >= TT * B_) return;
    ULL k = g_keys[i];
    unsigned col = 0xFFFFFFFFu - (unsigned)(k & 0xFFFFFFFFull);
    int t = i >> 6, b = i & 63;
    out[b * TT + t] = (float)col;
}

// ---------------- launch ----------------
extern "C" void kernel_launch(void* const* d_in, const int* in_sizes, int n_in,
                              void* d_out, int out_size) {
    const int*   ids    = (const int*)  d_in[0];
    const float* istate = (const float*)d_in[1];
    const float* emb    = (const float*)d_in[2];
    const float* encW   = (const float*)d_in[3];
    const float* Wih0   = (const float*)d_in[4];
    const float* Whh0   = (const float*)d_in[5];
    const float* bih0   = (const float*)d_in[6];
    const float* bhh0   = (const float*)d_in[7];
    const float* Wih1   = (const float*)d_in[8];
    const float* Whh1   = (const float*)d_in[9];
    const float* bih1   = (const float*)d_in[10];
    const float* bhh1   = (const float*)d_in[11];
    const float* PW     = (const float*)d_in[12];
    const float* PB     = (const float*)d_in[13];
    float* out = (float*)d_out;

    pack_kernel<<<(G4 * 2048) / 256, 256>>>(Wih0, Whh0, Wih1, Whh1, bih0, bhh0, bih1, bhh1);
    h0init_kernel<<<32, 128>>>(istate, encW);
    embx_kernel<<<dim3(TT, 32), 256>>>(ids, emb);
    for (int t = 0; t < TT; t++) {
        cell_kernel<<<128, 256>>>(t, 0);
        cell_kernel<<<128, 256>>>(t, 1);
    }
    proj_kernel<<<dim3(TT, 250), 256>>>(PW, PB, out);
    preds_kernel<<<16, 256>>>(out);
}

// round 5
// speedup vs baseline: 1.0550x; 1.0550x over previous
#include <cuda_runtime.h>
#include <math.h>

typedef unsigned long long ULL;

// ---------------- constants ----------------
#define B_   64
#define TT   63          // time steps actually computed (T-1)
#define EE   512
#define HH   1024
#define VV   32000
#define G4   4096        // 4*H

// ---------------- scratch (device globals; no allocation) ----------------
__device__ float g_Wih0p[G4 * EE];          //  8.4 MB  gate-interleaved W_ih0
__device__ float g_Whh0p[G4 * HH];          // 16.8 MB  gate-interleaved W_hh0
__device__ float g_W1cat[G4 * 2 * HH];      // 33.6 MB  [W_ih1 | W_hh1] interleaved
__device__ float g_b0p[G4];
__device__ float g_b1p[G4];
__device__ float g_G0x[TT * B_ * G4];       // 66 MB    x-side layer0 gates (+bias)
__device__ float g_H1 [TT * B_ * HH];       // 16.5 MB  h1 per step
__device__ float g_h0buf[2][B_ * HH];
__device__ float g_h1buf[2][B_ * HH];
__device__ float g_c0s[B_ * HH];
__device__ float g_c1s[B_ * HH];
__device__ ULL   g_keys[TT * B_];           // packed argmax keys, indexed t*64+b

// ---------------- helpers ----------------
static __device__ __forceinline__ ULL dup2(float b) {
    ULL r; unsigned u = __float_as_uint(b);
    asm("mov.b64 %0, {%1, %1};" : "=l"(r) : "r"(u));
    return r;
}
static __device__ __forceinline__ void fma2(ULL& acc, ULL a, ULL b) {
    asm("fma.rn.f32x2 %0, %1, %2, %0;" : "+l"(acc) : "l"(a), "l"(b));
}
static __device__ __forceinline__ ULL mk2(float x, float y) {
    ULL r;
    asm("mov.b64 %0, {%1, %2};" : "=l"(r)
        : "r"(__float_as_uint(x)), "r"(__float_as_uint(y)));
    return r;
}
static __device__ __forceinline__ float selh(ULL u, int hi) {
    return __uint_as_float(hi ? (unsigned)(u >> 32) : (unsigned)u);
}
static __device__ __forceinline__ float sigf(float x) { return 1.0f / (1.0f + expf(-x)); }
static __device__ __forceinline__ unsigned fordu(float v) {
    unsigned u = __float_as_uint(v);
    return u ^ (((int)u >> 31) | 0x80000000u);
}
static __device__ __forceinline__ ULL mkkey(float v, int col) {
    return ((ULL)fordu(v) << 32) | (ULL)(0xFFFFFFFFu - (unsigned)col);
}

// ---------------- 1) pack / init ----------------
__global__ void pack_kernel(const float* __restrict__ Wih0, const float* __restrict__ Whh0,
                            const float* __restrict__ Wih1, const float* __restrict__ Whh1,
                            const float* __restrict__ bih0, const float* __restrict__ bhh0,
                            const float* __restrict__ bih1, const float* __restrict__ bhh1) {
    int i = blockIdx.x * 256 + threadIdx.x;           // covers 4096*2048
    if (i < TT * B_) g_keys[i] = 0ull;
    int rp  = i >> 11;                                // new (interleaved) row
    int k   = i & 2047;
    int old = ((rp & 3) << 10) + (rp >> 2);           // gate*1024 + hidden
    g_W1cat[i] = (k < HH) ? Wih1[old * HH + k] : Whh1[old * HH + (k - HH)];
    if (k < EE) g_Wih0p[rp * EE + k] = Wih0[old * EE + k];
    if (k < HH) g_Whh0p[rp * HH + k] = Whh0[old * HH + k];
    if (k == 0) {
        g_b0p[rp] = bih0[old] + bhh0[old];
        g_b1p[rp] = bih1[old] + bhh1[old];
    }
}

// ---------------- 2) h0 = initial_state @ enc_proj_W^T  (also c0,h1,c1) ----------------
// tile 64x32, 128 threads, grid 32, K=2048  (small one-time kernel, kept simple)
__global__ __launch_bounds__(128) void h0init_kernel(const float* __restrict__ S,
                                                     const float* __restrict__ EW) {
    __shared__ float A_sm[32 * 66];
    __shared__ float B_sm[32 * 36];
    int tid = threadIdx.x, tr = tid >> 3, tc = tid & 7;
    int cb = blockIdx.x * 32;
    ULL acc[2][4] = {{0,0,0,0},{0,0,0,0}};
    float pA[16], pB[8];
    #pragma unroll
    for (int e = 0; e < 16; e++) { int idx = e*128+tid; pA[e] = S[(idx>>5)*2048 + (idx&31)]; }
    #pragma unroll
    for (int e = 0; e < 8;  e++) { int idx = e*128+tid; pB[e] = EW[(size_t)(cb+(idx>>5))*2048 + (idx&31)]; }
    for (int k0 = 0; k0 < 2048; k0 += 32) {
        __syncthreads();
        #pragma unroll
        for (int e = 0; e < 16; e++) { int idx = e*128+tid; A_sm[(idx&31)*66 + (idx>>5)] = pA[e]; }
        #pragma unroll
        for (int e = 0; e < 8;  e++) { int idx = e*128+tid; B_sm[(idx&31)*36 + (idx>>5)] = pB[e]; }
        __syncthreads();
        int kn = k0 + 32;
        if (kn < 2048) {
            #pragma unroll
            for (int e = 0; e < 16; e++) { int idx = e*128+tid; pA[e] = S[(idx>>5)*2048 + kn + (idx&31)]; }
            #pragma unroll
            for (int e = 0; e < 8;  e++) { int idx = e*128+tid; pB[e] = EW[(size_t)(cb+(idx>>5))*2048 + kn + (idx&31)]; }
        }
        #pragma unroll 8
        for (int kk = 0; kk < 32; kk++) {
            const ULL* ar = reinterpret_cast<const ULL*>(A_sm + kk * 66);
            ULL a0 = ar[2*tr], a1 = ar[2*tr+1];
            float4 bv = *reinterpret_cast<const float4*>(B_sm + kk*36 + 4*tc);
            ULL b0 = dup2(bv.x), b1 = dup2(bv.y), b2 = dup2(bv.z), b3 = dup2(bv.w);
            fma2(acc[0][0], a0, b0); fma2(acc[1][0], a1, b0);
            fma2(acc[0][1], a0, b1); fma2(acc[1][1], a1, b1);
            fma2(acc[0][2], a0, b2); fma2(acc[1][2], a1, b2);
            fma2(acc[0][3], a0, b3); fma2(acc[1][3], a1, b3);
        }
    }
    #pragma unroll
    for (int p = 0; p < 2; p++) {
        #pragma unroll
        for (int hi = 0; hi < 2; hi++) {
            int r = 4*tr + 2*p + hi;
            #pragma unroll
            for (int c = 0; c < 4; c++) {
                int col = cb + 4*tc + c;
                float v = selh(acc[p][c], hi);
                g_h0buf[0][r*HH + col] = v;
                g_c0s   [r*HH + col]   = v;
                g_h1buf[0][r*HH + col] = v;
                g_c1s   [r*HH + col]   = v;
            }
        }
    }
}

// ---------------- 3) G0x = emb[ids] @ Wih0p^T + b0p  ----------------
// tile 64x128, 256 threads (2 warps/SMSP, 2 CTAs/SM), grid (63, 32), K=512
// A duplicated pairs in smem, B natural col-pairs, swizzled smem layout.
__global__ __launch_bounds__(256, 2) void embx_kernel(const int* __restrict__ ids,
                                                      const float* __restrict__ emb) {
    __shared__ ULL   A_smd[32 * 66];
    __shared__ float B_sm [32 * 132];
    __shared__ int   ids_sm[B_];
    int tid = threadIdx.x, tr = tid >> 3, tc = tid & 7;
    int t = blockIdx.x, cb = blockIdx.y * 128;
    if (tid < B_) ids_sm[tid] = ids[tid * 64 + t];
    __syncthreads();
    ULL acc[2][8];
    #pragma unroll
    for (int r = 0; r < 2; r++)
        #pragma unroll
        for (int c = 0; c < 8; c++) acc[r][c] = 0ull;

    // precomputed per-element copy indices
    int aS[8], bS[16];                 // smem target indices
    size_t aG[8]; int bR[16], bK[16];  // global offsets
    #pragma unroll
    for (int e = 0; e < 8; e++) {
        int idx = e*256+tid; int k = idx&31, row = idx>>5;
        aS[e] = k*66 + (((row>>1) ^ (k>>3)) << 1) + (row&1);
        aG[e] = (size_t)ids_sm[row] * EE + k;
    }
    #pragma unroll
    for (int e = 0; e < 16; e++) {
        int idx = e*256+tid; int k = idx&31, c = idx>>5;
        bS[e] = k*132 + (((c>>2) ^ (k>>3)) << 2) + (c&3);
        bR[e] = cb + c; bK[e] = k;
    }

    float pA[8], pB[16];
    #pragma unroll
    for (int e = 0; e < 8;  e++) pA[e] = emb[aG[e]];
    #pragma unroll
    for (int e = 0; e < 16; e++) pB[e] = g_Wih0p[(size_t)bR[e]*EE + bK[e]];

    for (int k0 = 0; k0 < EE; k0 += 32) {
        __syncthreads();
        #pragma unroll
        for (int e = 0; e < 8;  e++) A_smd[aS[e]] = dup2(pA[e]);
        #pragma unroll
        for (int e = 0; e < 16; e++) B_sm[bS[e]]  = pB[e];
        __syncthreads();
        int kn = k0 + 32;
        if (kn < EE) {
            #pragma unroll
            for (int e = 0; e < 8;  e++) pA[e] = emb[aG[e] + kn];
            #pragma unroll
            for (int e = 0; e < 16; e++) pB[e] = g_Wih0p[(size_t)bR[e]*EE + kn + bK[e]];
        }
        #pragma unroll
        for (int sb = 0; sb < 4; sb++) {
            const ULL*   pa = A_smd + ((tr ^ sb) << 1);
            const float* pb = B_sm  + ((tc ^ sb) << 2);
            #pragma unroll
            for (int k2 = 0; k2 < 8; k2++) {
                int kk = sb*8 + k2;
                ulonglong2 av = *reinterpret_cast<const ulonglong2*>(pa + kk*66);
                #pragma unroll
                for (int jj = 0; jj < 4; jj++) {
                    ulonglong2 bv = *reinterpret_cast<const ulonglong2*>(pb + kk*132 + 32*jj);
                    fma2(acc[0][2*jj],   av.x, bv.x); fma2(acc[0][2*jj+1], av.x, bv.y);
                    fma2(acc[1][2*jj],   av.y, bv.x); fma2(acc[1][2*jj+1], av.y, bv.y);
                }
            }
        }
    }
    float* outp = g_G0x + (size_t)(t * B_) * G4;
    #pragma unroll
    for (int jj = 0; jj < 4; jj++) {
        int col0 = cb + 4*tc + 32*jj;
        float4 bb = *reinterpret_cast<const float4*>(g_b0p + col0);
        #pragma unroll
        for (int r = 0; r < 2; r++) {
            int row = 2*tr + r;
            float4 v;
            v.x = selh(acc[r][2*jj],0)   + bb.x;
            v.y = selh(acc[r][2*jj],1)   + bb.y;
            v.z = selh(acc[r][2*jj+1],0) + bb.z;
            v.w = selh(acc[r][2*jj+1],1) + bb.w;
            *reinterpret_cast<float4*>(outp + (size_t)row*G4 + col0) = v;
        }
    }
}

// ---------------- 4) fused LSTM cell step (one layer) ----------------
// tile 64x32 gate-cols, 256 threads (2 warps/SMSP), grid 128, smem double-buffered
__global__ __launch_bounds__(256) void cell_kernel(int t, int layer) {
    __shared__ ULL   Abuf[2][32 * 66];
    __shared__ float Bbuf[2][32 * 36];
    int tid = threadIdx.x;
    int tr = tid >> 3;      // row pair 0..31
    int tc = tid & 7;       // 4 gate cols
    int cb = blockIdx.x * 32;
    int in = t & 1, out = in ^ 1;

    const float *A1, *A2, *W;
    float *cst, *hout, *hcopy = nullptr;
    int K;
    if (layer == 0) {
        A1 = g_h0buf[in]; A2 = A1; W = g_Whh0p; K = HH;
        cst = g_c0s; hout = g_h0buf[out];
    } else {
        A1 = g_h0buf[out]; A2 = g_h1buf[in]; W = g_W1cat; K = 2 * HH;
        cst = g_c1s; hout = g_h1buf[out];
        hcopy = g_H1 + (size_t)(t * B_) * HH;
    }

    int gc0 = cb + 4 * tc;
    ULL acc[2][2];
    if (layer == 0) {
        const float* initp = g_G0x + (size_t)(t * B_) * G4;
        float4 i0 = *reinterpret_cast<const float4*>(initp + (size_t)(2*tr)   * G4 + gc0);
        float4 i1 = *reinterpret_cast<const float4*>(initp + (size_t)(2*tr+1) * G4 + gc0);
        acc[0][0] = mk2(i0.x, i0.y); acc[0][1] = mk2(i0.z, i0.w);
        acc[1][0] = mk2(i1.x, i1.y); acc[1][1] = mk2(i1.z, i1.w);
    } else {
        float4 bb = *reinterpret_cast<const float4*>(g_b1p + gc0);
        acc[0][0] = mk2(bb.x, bb.y); acc[1][0] = acc[0][0];
        acc[0][1] = mk2(bb.z, bb.w); acc[1][1] = acc[0][1];
    }

    // precomputed copy indices
    int aS[8], aR[8], aK[8], bS[4]; size_t bG[4];
    #pragma unroll
    for (int e = 0; e < 8; e++) {
        int idx = e*256+tid; int k = idx&31, row = idx>>5;
        aS[e] = k*66 + (((row>>1) ^ (k>>3)) << 1) + (row&1);
        aR[e] = row * HH; aK[e] = k;
    }
    #pragma unroll
    for (int e = 0; e < 4; e++) {
        int idx = e*256+tid; int k = idx&31, c = idx>>5;
        bS[e] = k*36 + (((c>>2) ^ (k>>3)) << 2) + (c&3);
        bG[e] = (size_t)(cb + c) * K + k;
    }

    int nb = K >> 5;
    float pA[8], pB[4];
    // load + store block 0
    #pragma unroll
    for (int e = 0; e < 8; e++) pA[e] = A1[aR[e] + aK[e]];
    #pragma unroll
    for (int e = 0; e < 4; e++) pB[e] = W[bG[e]];
    #pragma unroll
    for (int e = 0; e < 8; e++) Abuf[0][aS[e]] = dup2(pA[e]);
    #pragma unroll
    for (int e = 0; e < 4; e++) Bbuf[0][bS[e]] = pB[e];
    // load block 1
    {
        const float* Asrc = (32 < HH) ? (A1 + 32) : (A2 + (32 - HH));
        #pragma unroll
        for (int e = 0; e < 8; e++) pA[e] = Asrc[aR[e] + aK[e]];
        #pragma unroll
        for (int e = 0; e < 4; e++) pB[e] = W[bG[e] + 32];
    }

    for (int blk = 0; blk < nb; blk++) {
        __syncthreads();
        int cur = blk & 1, nxt = cur ^ 1;
        if (blk + 1 < nb) {
            #pragma unroll
            for (int e = 0; e < 8; e++) Abuf[nxt][aS[e]] = dup2(pA[e]);
            #pragma unroll
            for (int e = 0; e < 4; e++) Bbuf[nxt][bS[e]] = pB[e];
            if (blk + 2 < nb) {
                int k0 = (blk + 2) << 5;
                const float* Asrc = (k0 < HH) ? (A1 + k0) : (A2 + (k0 - HH));
                #pragma unroll
                for (int e = 0; e < 8; e++) pA[e] = Asrc[aR[e] + aK[e]];
                #pragma unroll
                for (int e = 0; e < 4; e++) pB[e] = W[bG[e] + k0];
            }
        }
        const ULL*   Ab = Abuf[cur];
        const float* Bb = Bbuf[cur];
        #pragma unroll
        for (int sb = 0; sb < 4; sb++) {
            const ULL*   pa = Ab + ((tr ^ sb) << 1);
            const float* pb = Bb + ((tc ^ sb) << 2);
            #pragma unroll
            for (int k2 = 0; k2 < 8; k2++) {
                int kk = sb*8 + k2;
                ulonglong2 av = *reinterpret_cast<const ulonglong2*>(pa + kk*66);
                ulonglong2 bv = *reinterpret_cast<const ulonglong2*>(pb + kk*36);
                fma2(acc[0][0], av.x, bv.x); fma2(acc[0][1], av.x, bv.y);
                fma2(acc[1][0], av.y, bv.x); fma2(acc[1][1], av.y, bv.y);
            }
        }
    }

    // fused LSTM activation epilogue (thread owns gates i,f,g,o of hidden j)
    int j = (cb >> 2) + tc;
    #pragma unroll
    for (int r = 0; r < 2; r++) {
        int row = 2*tr + r;
        float iv = selh(acc[r][0], 0);
        float fv = selh(acc[r][0], 1);
        float gv = selh(acc[r][1], 0);
        float ov = selh(acc[r][1], 1);
        float cold = cst[row*HH + j];
        float cn = sigf(fv) * cold + sigf(iv) * tanhf(gv);
        float h  = sigf(ov) * tanhf(cn);
        cst [row*HH + j] = cn;
        hout[row*HH + j] = h;
        if (hcopy) hcopy[row*HH + j] = h;
    }
}

// ---------------- 5) logits = H1 @ proj_W^T + b, fused argmax ----------------
// tile 64x128, 256 threads, 2 CTAs/SM, grid (63, 250), K=1024
__global__ __launch_bounds__(256, 2) void proj_kernel(const float* __restrict__ PW,
                                                      const float* __restrict__ PB,
                                                      float* __restrict__ out) {
    __shared__ ULL   A_smd[32 * 66];
    __shared__ float B_sm [32 * 132];
    int tid = threadIdx.x, tr = tid >> 3, tc = tid & 7;
    int t = blockIdx.x, cb = blockIdx.y * 128;
    const float* A = g_H1 + (size_t)(t * B_) * HH;
    ULL acc[2][8];
    #pragma unroll
    for (int r = 0; r < 2; r++)
        #pragma unroll
        for (int c = 0; c < 8; c++) acc[r][c] = 0ull;

    int aS[8], aR[8], aK[8], bS[16]; size_t bG[16];
    #pragma unroll
    for (int e = 0; e < 8; e++) {
        int idx = e*256+tid; int k = idx&31, row = idx>>5;
        aS[e] = k*66 + (((row>>1) ^ (k>>3)) << 1) + (row&1);
        aR[e] = row * HH; aK[e] = k;
    }
    #pragma unroll
    for (int e = 0; e < 16; e++) {
        int idx = e*256+tid; int k = idx&31, c = idx>>5;
        bS[e] = k*132 + (((c>>2) ^ (k>>3)) << 2) + (c&3);
        bG[e] = (size_t)(cb + c) * HH + k;
    }

    float pA[8], pB[16];
    #pragma unroll
    for (int e = 0; e < 8;  e++) pA[e] = A[aR[e] + aK[e]];
    #pragma unroll
    for (int e = 0; e < 16; e++) pB[e] = PW[bG[e]];

    for (int k0 = 0; k0 < HH; k0 += 32) {
        __syncthreads();
        #pragma unroll
        for (int e = 0; e < 8;  e++) A_smd[aS[e]] = dup2(pA[e]);
        #pragma unroll
        for (int e = 0; e < 16; e++) B_sm[bS[e]]  = pB[e];
        __syncthreads();
        int kn = k0 + 32;
        if (kn < HH) {
            #pragma unroll
            for (int e = 0; e < 8;  e++) pA[e] = A[aR[e] + kn + aK[e]];
            #pragma unroll
            for (int e = 0; e < 16; e++) pB[e] = PW[bG[e] + kn];
        }
        #pragma unroll
        for (int sb = 0; sb < 4; sb++) {
            const ULL*   pa = A_smd + ((tr ^ sb) << 1);
            const float* pb = B_sm  + ((tc ^ sb) << 2);
            #pragma unroll
            for (int k2 = 0; k2 < 8; k2++) {
                int kk = sb*8 + k2;
                ulonglong2 av = *reinterpret_cast<const ulonglong2*>(pa + kk*66);
                #pragma unroll
                for (int jj = 0; jj < 4; jj++) {
                    ulonglong2 bv = *reinterpret_cast<const ulonglong2*>(pb + kk*132 + 32*jj);
                    fma2(acc[0][2*jj],   av.x, bv.x); fma2(acc[0][2*jj+1], av.x, bv.y);
                    fma2(acc[1][2*jj],   av.y, bv.x); fma2(acc[1][2*jj+1], av.y, bv.y);
                }
            }
        }
    }

    float* lout = out + TT * B_;                 // logits after preds
    ULL rowkey[2] = {0ull, 0ull};
    #pragma unroll
    for (int jj = 0; jj < 4; jj++) {
        int col0 = cb + 4*tc + 32*jj;
        float4 bb = *reinterpret_cast<const float4*>(PB + col0);
        #pragma unroll
        for (int r = 0; r < 2; r++) {
            int b = 2*tr + r;
            float4 v;
            v.x = selh(acc[r][2*jj],0)   + bb.x;
            v.y = selh(acc[r][2*jj],1)   + bb.y;
            v.z = selh(acc[r][2*jj+1],0) + bb.z;
            v.w = selh(acc[r][2*jj+1],1) + bb.w;
            *reinterpret_cast<float4*>(lout + ((size_t)b * TT + t) * VV + col0) = v;
            ULL key = mkkey(v.x, col0);
            ULL k2  = mkkey(v.y, col0 + 1); if (k2 > key) key = k2;
            k2      = mkkey(v.z, col0 + 2); if (k2 > key) key = k2;
            k2      = mkkey(v.w, col0 + 3); if (k2 > key) key = k2;
            if (key > rowkey[r]) rowkey[r] = key;
        }
    }
    #pragma unroll
    for (int r = 0; r < 2; r++) {
        ULL key = rowkey[r];
        #pragma unroll
        for (int off = 4; off > 0; off >>= 1) {   // reduce across tc lanes (bits 0..2)
            ULL o = __shfl_xor_sync(0xFFFFFFFFu, key, off);
            if (o > key) key = o;
        }
        if (tc == 0) atomicMax(&g_keys[t * B_ + (2*tr + r)], key);
    }
}

// ---------------- 6) finalize preds ----------------
__global__ void preds_kernel(float* __restrict__ out) {
    int i = blockIdx.x * 256 + threadIdx.x;
    if (i >= TT * B_) return;
    ULL k = g_keys[i];
    unsigned col = 0xFFFFFFFFu - (unsigned)(k & 0xFFFFFFFFull);
    int t = i >> 6, b = i & 63;
    out[b * TT + t] = (float)col;
}

// ---------------- launch ----------------
extern "C" void kernel_launch(void* const* d_in, const int* in_sizes, int n_in,
                              void* d_out, int out_size) {
    const int*   ids    = (const int*)  d_in[0];
    const float* istate = (const float*)d_in[1];
    const float* emb    = (const float*)d_in[2];
    const float* encW   = (const float*)d_in[3];
    const float* Wih0   = (const float*)d_in[4];
    const float* Whh0   = (const float*)d_in[5];
    const float* bih0   = (const float*)d_in[6];
    const float* bhh0   = (const float*)d_in[7];
    const float* Wih1   = (const float*)d_in[8];
    const float* Whh1   = (const float*)d_in[9];
    const float* bih1   = (const float*)d_in[10];
    const float* bhh1   = (const float*)d_in[11];
    const float* PW     = (const float*)d_in[12];
    const float* PB     = (const float*)d_in[13];
    float* out = (float*)d_out;

    pack_kernel<<<(G4 * 2048) / 256, 256>>>(Wih0, Whh0, Wih1, Whh1, bih0, bhh0, bih1, bhh1);
    h0init_kernel<<<32, 128>>>(istate, encW);
    embx_kernel<<<dim3(TT, 32), 256>>>(ids, emb);
    for (int t = 0; t < TT; t++) {
        cell_kernel<<<128, 256>>>(t, 0);
        cell_kernel<<<128, 256>>>(t, 1);
    }
    proj_kernel<<<dim3(TT, 250), 256>>>(PW, PB, out);
    preds_kernel<<<16, 256>>>(out);
}

// round 6
// speedup vs baseline: 1.1630x; 1.1024x over previous
#include <cuda_runtime.h>
#include <math.h>

typedef unsigned long long ULL;
typedef unsigned int uint;

// ---------------- constants ----------------
#define B_   64
#define TT   63          // time steps actually computed (T-1)
#define EE   512
#define HH   1024
#define VV   32000
#define G4   4096        // 4*H

// ---------------- scratch (device globals; no allocation) ----------------
__device__ float g_Wih0p[G4 * EE];          //  8.4 MB  gate-interleaved W_ih0
__device__ float g_Whh0p[G4 * HH];          // 16.8 MB  gate-interleaved W_hh0
__device__ float g_W1cat[G4 * 2 * HH];      // 33.6 MB  [W_ih1 | W_hh1] interleaved
__device__ float g_b0p[G4];
__device__ float g_b1p[G4];
__device__ float g_G0x[TT * B_ * G4];       // 66 MB    x-side layer0 gates (+bias)
__device__ float g_H1 [TT * B_ * HH];       // 16.5 MB  h1 per step
__device__ float g_h0buf[2][B_ * HH];
__device__ float g_h1buf[2][B_ * HH];
__device__ float g_c0s[B_ * HH];
__device__ float g_c1s[B_ * HH];
__device__ ULL   g_keys[TT * B_];           // packed argmax keys, indexed t*64+b

// ---------------- helpers ----------------
static __device__ __forceinline__ void fma2(ULL& acc, ULL a, ULL b) {
    asm("fma.rn.f32x2 %0, %1, %2, %0;" : "+l"(acc) : "l"(a), "l"(b));
}
static __device__ __forceinline__ ULL mk2(float x, float y) {
    ULL r;
    asm("mov.b64 %0, {%1, %2};" : "=l"(r)
        : "r"(__float_as_uint(x)), "r"(__float_as_uint(y)));
    return r;
}
static __device__ __forceinline__ float selh(ULL u, int hi) {
    return __uint_as_float(hi ? (unsigned)(u >> 32) : (unsigned)u);
}
static __device__ __forceinline__ float foldp(ULL u) {   // even-k part + odd-k part
    return selh(u, 0) + selh(u, 1);
}
static __device__ __forceinline__ ULL dup2(float b) {
    ULL r; unsigned u = __float_as_uint(b);
    asm("mov.b64 %0, {%1, %1};" : "=l"(r) : "r"(u));
    return r;
}
static __device__ __forceinline__ float sigf(float x) { return 1.0f / (1.0f + expf(-x)); }
static __device__ __forceinline__ unsigned fordu(float v) {
    unsigned u = __float_as_uint(v);
    return u ^ (((int)u >> 31) | 0x80000000u);
}
static __device__ __forceinline__ ULL mkkey(float v, int col) {
    return ((ULL)fordu(v) << 32) | (ULL)(0xFFFFFFFFu - (unsigned)col);
}

// ---------------- 1) pack / init ----------------
__global__ void pack_kernel(const float* __restrict__ Wih0, const float* __restrict__ Whh0,
                            const float* __restrict__ Wih1, const float* __restrict__ Whh1,
                            const float* __restrict__ bih0, const float* __restrict__ bhh0,
                            const float* __restrict__ bih1, const float* __restrict__ bhh1) {
    int i = blockIdx.x * 256 + threadIdx.x;           // covers 4096*2048
    if (i < TT * B_) g_keys[i] = 0ull;
    int rp  = i >> 11;                                // new (interleaved) row
    int k   = i & 2047;
    int old = ((rp & 3) << 10) + (rp >> 2);           // gate*1024 + hidden
    g_W1cat[i] = (k < HH) ? Wih1[old * HH + k] : Whh1[old * HH + (k - HH)];
    if (k < EE) g_Wih0p[rp * EE + k] = Wih0[old * EE + k];
    if (k < HH) g_Whh0p[rp * HH + k] = Whh0[old * HH + k];
    if (k == 0) {
        g_b0p[rp] = bih0[old] + bhh0[old];
        g_b1p[rp] = bih1[old] + bhh1[old];
    }
}

// ---------------- 2) h0 = initial_state @ enc_proj_W^T  (also c0,h1,c1) ----------------
// small one-time kernel (kept from R2, known-correct)
__global__ __launch_bounds__(128) void h0init_kernel(const float* __restrict__ S,
                                                     const float* __restrict__ EW) {
    __shared__ float A_sm[32 * 66];
    __shared__ float B_sm[32 * 36];
    int tid = threadIdx.x, tr = tid >> 3, tc = tid & 7;
    int cb = blockIdx.x * 32;
    ULL acc[2][4] = {{0,0,0,0},{0,0,0,0}};
    float pA[16], pB[8];
    #pragma unroll
    for (int e = 0; e < 16; e++) { int idx = e*128+tid; pA[e] = S[(idx>>5)*2048 + (idx&31)]; }
    #pragma unroll
    for (int e = 0; e < 8;  e++) { int idx = e*128+tid; pB[e] = EW[(size_t)(cb+(idx>>5))*2048 + (idx&31)]; }
    for (int k0 = 0; k0 < 2048; k0 += 32) {
        __syncthreads();
        #pragma unroll
        for (int e = 0; e < 16; e++) { int idx = e*128+tid; A_sm[(idx&31)*66 + (idx>>5)] = pA[e]; }
        #pragma unroll
        for (int e = 0; e < 8;  e++) { int idx = e*128+tid; B_sm[(idx&31)*36 + (idx>>5)] = pB[e]; }
        __syncthreads();
        int kn = k0 + 32;
        if (kn < 2048) {
            #pragma unroll
            for (int e = 0; e < 16; e++) { int idx = e*128+tid; pA[e] = S[(idx>>5)*2048 + kn + (idx&31)]; }
            #pragma unroll
            for (int e = 0; e < 8;  e++) { int idx = e*128+tid; pB[e] = EW[(size_t)(cb+(idx>>5))*2048 + kn + (idx&31)]; }
        }
        #pragma unroll 8
        for (int kk = 0; kk < 32; kk++) {
            const ULL* ar = reinterpret_cast<const ULL*>(A_sm + kk * 66);
            ULL a0 = ar[2*tr], a1 = ar[2*tr+1];
            float4 bv = *reinterpret_cast<const float4*>(B_sm + kk*36 + 4*tc);
            ULL b0 = dup2(bv.x), b1 = dup2(bv.y), b2 = dup2(bv.z), b3 = dup2(bv.w);
            fma2(acc[0][0], a0, b0); fma2(acc[1][0], a1, b0);
            fma2(acc[0][1], a0, b1); fma2(acc[1][1], a1, b1);
            fma2(acc[0][2], a0, b2); fma2(acc[1][2], a1, b2);
            fma2(acc[0][3], a0, b3); fma2(acc[1][3], a1, b3);
        }
    }
    #pragma unroll
    for (int p = 0; p < 2; p++) {
        #pragma unroll
        for (int hi = 0; hi < 2; hi++) {
            int r = 4*tr + 2*p + hi;
            #pragma unroll
            for (int c = 0; c < 4; c++) {
                int col = cb + 4*tc + c;
                float v = selh(acc[p][c], hi);
                g_h0buf[0][r*HH + col] = v;
                g_c0s   [r*HH + col]   = v;
                g_h1buf[0][r*HH + col] = v;
                g_c1s   [r*HH + col]   = v;
            }
        }
    }
}

// ==================================================================================
// k-pair GEMM kernels: acc pairs are (sum over even k, sum over odd k); no operand
// duplication; A read via warp-broadcast ulonglong2; XOR swizzle for 2-wf STS.
// ==================================================================================

// ---------------- 3) G0x = emb[ids] @ Wih0p^T + b0p ----------------
// tile 64x128, 256 threads, grid (63, 32), K=512, K-block=32 (16 kp)
__global__ __launch_bounds__(256) void embx_kernel(const int* __restrict__ ids,
                                                   const float* __restrict__ emb) {
    __shared__ ULL A2[16 * 64];    // [kp][row^swz]  8 KB
    __shared__ ULL B2[16 * 128];   // [kp][col^swz] 16 KB
    __shared__ int ids_sm[B_];
    int tid = threadIdx.x, ty = tid >> 5, tx = tid & 31;
    int t = blockIdx.x, cb = blockIdx.y * 128;
    if (tid < B_) ids_sm[tid] = ids[tid * 64 + t];
    __syncthreads();

    ULL acc[8][4];
    #pragma unroll
    for (int r = 0; r < 8; r++)
        #pragma unroll
        for (int c = 0; c < 4; c++) acc[r][c] = 0ull;

    int lkp = tid & 15;            // load kp
    int lr  = tid >> 4;            // 0..15
    int lsw = (lkp << 1) & 30;
    uint aG[4];
    #pragma unroll
    for (int e = 0; e < 4; e++) aG[e] = (uint)ids_sm[lr + 16*e] * EE + 2*lkp;
    uint bG = (uint)(cb + lr) * EE + 2*lkp;     // + 16e*EE

    float2 pA[4], pB[8];
    #pragma unroll
    for (int e = 0; e < 4; e++) pA[e] = *reinterpret_cast<const float2*>(emb + aG[e]);
    #pragma unroll
    for (int e = 0; e < 8; e++) pB[e] = *reinterpret_cast<const float2*>(g_Wih0p + bG + (uint)(16*e)*EE);

    for (int k0 = 0; k0 < EE; k0 += 32) {
        __syncthreads();
        #pragma unroll
        for (int e = 0; e < 4; e++) A2[lkp*64  + ((lr + 16*e) ^ lsw)] = *reinterpret_cast<ULL*>(&pA[e]);
        #pragma unroll
        for (int e = 0; e < 8; e++) B2[lkp*128 + ((lr + 16*e) ^ lsw)] = *reinterpret_cast<ULL*>(&pB[e]);
        __syncthreads();
        int kn = k0 + 32;
        if (kn < EE) {
            #pragma unroll
            for (int e = 0; e < 4; e++) pA[e] = *reinterpret_cast<const float2*>(emb + aG[e] + kn);
            #pragma unroll
            for (int e = 0; e < 8; e++) pB[e] = *reinterpret_cast<const float2*>(g_Wih0p + bG + kn + (uint)(16*e)*EE);
        }
        #pragma unroll
        for (int kp = 0; kp < 16; kp++) {
            int s = (kp << 1) & 30;
            ulonglong2 bv0 = *reinterpret_cast<const ulonglong2*>(&B2[kp*128 + ((4*tx) ^ s)]);
            ulonglong2 bv1 = *reinterpret_cast<const ulonglong2*>(&B2[kp*128 + ((4*tx + 2) ^ s)]);
            #pragma unroll
            for (int j = 0; j < 4; j++) {
                ulonglong2 av = *reinterpret_cast<const ulonglong2*>(&A2[kp*64 + ((8*ty + 2*j) ^ s)]);
                fma2(acc[2*j][0],   av.x, bv0.x); fma2(acc[2*j][1],   av.x, bv0.y);
                fma2(acc[2*j][2],   av.x, bv1.x); fma2(acc[2*j][3],   av.x, bv1.y);
                fma2(acc[2*j+1][0], av.y, bv0.x); fma2(acc[2*j+1][1], av.y, bv0.y);
                fma2(acc[2*j+1][2], av.y, bv1.x); fma2(acc[2*j+1][3], av.y, bv1.y);
            }
        }
    }
    float* outp = g_G0x + (size_t)(t * B_) * G4;
    int col0 = cb + 4*tx;
    float4 bb = *reinterpret_cast<const float4*>(g_b0p + col0);
    #pragma unroll
    for (int rr = 0; rr < 8; rr++) {
        int row = 8*ty + rr;
        float4 v;
        v.x = foldp(acc[rr][0]) + bb.x;
        v.y = foldp(acc[rr][1]) + bb.y;
        v.z = foldp(acc[rr][2]) + bb.z;
        v.w = foldp(acc[rr][3]) + bb.w;
        *reinterpret_cast<float4*>(outp + (size_t)row*G4 + col0) = v;
    }
}

// ---------------- 4) fused LSTM cell step (one layer) ----------------
// tile 64x32 gate-cols, 256 threads, grid 128, K-block=64 (32 kp), double-buffered
__global__ __launch_bounds__(256) void cell_kernel(int t, int layer) {
    __shared__ ULL A2[2][32 * 64];   // 2 x 16 KB
    __shared__ ULL B2[2][32 * 32];   // 2 x  8 KB
    int tid = threadIdx.x;
    int w  = tid >> 5, l = tid & 31;
    int rp = l >> 3;                 // 0..3 -> rows 8w+2rp, +1
    int cg = l & 7;                  // 4 cols at 4cg
    int cb = blockIdx.x * 32;
    int in = t & 1, out = in ^ 1;

    const float *A1, *A2g, *W;
    float *cst, *hout, *hcopy = nullptr;
    int K;
    if (layer == 0) {
        A1 = g_h0buf[in]; A2g = A1; W = g_Whh0p; K = HH;
        cst = g_c0s; hout = g_h0buf[out];
    } else {
        A1 = g_h0buf[out]; A2g = g_h1buf[in]; W = g_W1cat; K = 2 * HH;
        cst = g_c1s; hout = g_h1buf[out];
        hcopy = g_H1 + (size_t)(t * B_) * HH;
    }

    int r0 = 8*w + 2*rp;
    int gc0 = cb + 4*cg;
    ULL acc[2][4];
    if (layer == 0) {
        const float* initp = g_G0x + (size_t)(t * B_) * G4;
        float4 i0 = *reinterpret_cast<const float4*>(initp + (size_t)r0     * G4 + gc0);
        float4 i1 = *reinterpret_cast<const float4*>(initp + (size_t)(r0+1) * G4 + gc0);
        acc[0][0] = mk2(i0.x, 0.f); acc[0][1] = mk2(i0.y, 0.f);
        acc[0][2] = mk2(i0.z, 0.f); acc[0][3] = mk2(i0.w, 0.f);
        acc[1][0] = mk2(i1.x, 0.f); acc[1][1] = mk2(i1.y, 0.f);
        acc[1][2] = mk2(i1.z, 0.f); acc[1][3] = mk2(i1.w, 0.f);
    } else {
        float4 bb = *reinterpret_cast<const float4*>(g_b1p + gc0);
        acc[0][0] = mk2(bb.x, 0.f); acc[0][1] = mk2(bb.y, 0.f);
        acc[0][2] = mk2(bb.z, 0.f); acc[0][3] = mk2(bb.w, 0.f);
        acc[1][0] = acc[0][0]; acc[1][1] = acc[0][1];
        acc[1][2] = acc[0][2]; acc[1][3] = acc[0][3];
    }

    // load mapping: kp = tid&31, A rows = (tid>>5)+8e (e<8), B cols = (tid>>5)+8e (e<4)
    int lkp = l;                        // within warp kp == lane? no: kp = tid&31 == l
    int lsw = (lkp & 15) << 1;
    uint aBase = (uint)w * HH + 2*lkp;            // row w+8e -> + 8e*HH
    uint bBase = (uint)(cb + w) * K + 2*lkp;      // col w+8e -> + 8e*K

    int nb = K >> 6;
    float2 pA[8], pB[4];
    // block 0 load + store
    #pragma unroll
    for (int e = 0; e < 8; e++) pA[e] = *reinterpret_cast<const float2*>(A1 + aBase + (uint)(8*e)*HH);
    #pragma unroll
    for (int e = 0; e < 4; e++) pB[e] = *reinterpret_cast<const float2*>(W  + bBase + (uint)(8*e)*K);
    #pragma unroll
    for (int e = 0; e < 8; e++) A2[0][lkp*64 + ((w + 8*e) ^ lsw)] = *reinterpret_cast<ULL*>(&pA[e]);
    #pragma unroll
    for (int e = 0; e < 4; e++) B2[0][lkp*32 + ((w + 8*e) ^ lsw)] = *reinterpret_cast<ULL*>(&pB[e]);
    // block 1 loads into regs
    if (nb > 1) {
        const float* Asrc = (64 < HH) ? (A1 + 64) : (A2g + (64 - HH));
        #pragma unroll
        for (int e = 0; e < 8; e++) pA[e] = *reinterpret_cast<const float2*>(Asrc + aBase + (uint)(8*e)*HH);
        #pragma unroll
        for (int e = 0; e < 4; e++) pB[e] = *reinterpret_cast<const float2*>(W + bBase + 64 + (uint)(8*e)*K);
    }

    for (int blk = 0; blk < nb; blk++) {
        __syncthreads();
        int cur = blk & 1, nxt = cur ^ 1;
        if (blk + 1 < nb) {
            #pragma unroll
            for (int e = 0; e < 8; e++) A2[nxt][lkp*64 + ((w + 8*e) ^ lsw)] = *reinterpret_cast<ULL*>(&pA[e]);
            #pragma unroll
            for (int e = 0; e < 4; e++) B2[nxt][lkp*32 + ((w + 8*e) ^ lsw)] = *reinterpret_cast<ULL*>(&pB[e]);
            if (blk + 2 < nb) {
                int k0 = (blk + 2) << 6;
                const float* Asrc = (k0 < HH) ? (A1 + k0) : (A2g + (k0 - HH));
                #pragma unroll
                for (int e = 0; e < 8; e++) pA[e] = *reinterpret_cast<const float2*>(Asrc + aBase + (uint)(8*e)*HH);
                #pragma unroll
                for (int e = 0; e < 4; e++) pB[e] = *reinterpret_cast<const float2*>(W + bBase + k0 + (uint)(8*e)*K);
            }
        }
        const ULL* Ab = A2[cur];
        const ULL* Bb = B2[cur];
        #pragma unroll
        for (int kp = 0; kp < 32; kp++) {
            int s = (kp & 15) << 1;
            ulonglong2 av  = *reinterpret_cast<const ulonglong2*>(&Ab[kp*64 + (r0 ^ s)]);
            ulonglong2 bv0 = *reinterpret_cast<const ulonglong2*>(&Bb[kp*32 + ((4*cg) ^ s)]);
            ulonglong2 bv1 = *reinterpret_cast<const ulonglong2*>(&Bb[kp*32 + ((4*cg + 2) ^ s)]);
            fma2(acc[0][0], av.x, bv0.x); fma2(acc[0][1], av.x, bv0.y);
            fma2(acc[0][2], av.x, bv1.x); fma2(acc[0][3], av.x, bv1.y);
            fma2(acc[1][0], av.y, bv0.x); fma2(acc[1][1], av.y, bv0.y);
            fma2(acc[1][2], av.y, bv1.x); fma2(acc[1][3], av.y, bv1.y);
        }
    }

    // fused LSTM activation epilogue (thread owns gates i,f,g,o of hidden j, rows r0,r0+1)
    int j = (cb >> 2) + cg;
    #pragma unroll
    for (int r = 0; r < 2; r++) {
        int row = r0 + r;
        float iv = foldp(acc[r][0]);
        float fv = foldp(acc[r][1]);
        float gv = foldp(acc[r][2]);
        float ov = foldp(acc[r][3]);
        float cold = cst[row*HH + j];
        float cn = sigf(fv) * cold + sigf(iv) * tanhf(gv);
        float h  = sigf(ov) * tanhf(cn);
        cst [row*HH + j] = cn;
        hout[row*HH + j] = h;
        if (hcopy) hcopy[row*HH + j] = h;
    }
}

// ---------------- 5) logits = H1 @ proj_W^T + b, fused argmax ----------------
// tile 64x128, 256 threads, grid (63, 250), K=1024, K-block=32 (16 kp)
__global__ __launch_bounds__(256) void proj_kernel(const float* __restrict__ PW,
                                                   const float* __restrict__ PB,
                                                   float* __restrict__ out) {
    __shared__ ULL A2[16 * 64];    //  8 KB
    __shared__ ULL B2[16 * 128];   // 16 KB
    int tid = threadIdx.x, ty = tid >> 5, tx = tid & 31;
    int t = blockIdx.x, cb = blockIdx.y * 128;
    const float* A = g_H1 + (size_t)(t * B_) * HH;

    ULL acc[8][4];
    #pragma unroll
    for (int r = 0; r < 8; r++)
        #pragma unroll
        for (int c = 0; c < 4; c++) acc[r][c] = 0ull;

    int lkp = tid & 15;
    int lr  = tid >> 4;
    int lsw = (lkp << 1) & 30;
    uint aBase = (uint)lr * HH + 2*lkp;            // + 16e*HH
    uint bBase = (uint)(cb + lr) * HH + 2*lkp;     // + 16e*HH

    float2 pA[4], pB[8];
    #pragma unroll
    for (int e = 0; e < 4; e++) pA[e] = *reinterpret_cast<const float2*>(A  + aBase + (uint)(16*e)*HH);
    #pragma unroll
    for (int e = 0; e < 8; e++) pB[e] = *reinterpret_cast<const float2*>(PW + bBase + (uint)(16*e)*HH);

    for (int k0 = 0; k0 < HH; k0 += 32) {
        __syncthreads();
        #pragma unroll
        for (int e = 0; e < 4; e++) A2[lkp*64  + ((lr + 16*e) ^ lsw)] = *reinterpret_cast<ULL*>(&pA[e]);
        #pragma unroll
        for (int e = 0; e < 8; e++) B2[lkp*128 + ((lr + 16*e) ^ lsw)] = *reinterpret_cast<ULL*>(&pB[e]);
        __syncthreads();
        int kn = k0 + 32;
        if (kn < HH) {
            #pragma unroll
            for (int e = 0; e < 4; e++) pA[e] = *reinterpret_cast<const float2*>(A  + aBase + kn + (uint)(16*e)*HH);
            #pragma unroll
            for (int e = 0; e < 8; e++) pB[e] = *reinterpret_cast<const float2*>(PW + bBase + kn + (uint)(16*e)*HH);
        }
        #pragma unroll
        for (int kp = 0; kp < 16; kp++) {
            int s = (kp << 1) & 30;
            ulonglong2 bv0 = *reinterpret_cast<const ulonglong2*>(&B2[kp*128 + ((4*tx) ^ s)]);
            ulonglong2 bv1 = *reinterpret_cast<const ulonglong2*>(&B2[kp*128 + ((4*tx + 2) ^ s)]);
            #pragma unroll
            for (int j = 0; j < 4; j++) {
                ulonglong2 av = *reinterpret_cast<const ulonglong2*>(&A2[kp*64 + ((8*ty + 2*j) ^ s)]);
                fma2(acc[2*j][0],   av.x, bv0.x); fma2(acc[2*j][1],   av.x, bv0.y);
                fma2(acc[2*j][2],   av.x, bv1.x); fma2(acc[2*j][3],   av.x, bv1.y);
                fma2(acc[2*j+1][0], av.y, bv0.x); fma2(acc[2*j+1][1], av.y, bv0.y);
                fma2(acc[2*j+1][2], av.y, bv1.x); fma2(acc[2*j+1][3], av.y, bv1.y);
            }
        }
    }

    float* lout = out + TT * B_;                 // logits after preds
    int col0 = cb + 4*tx;
    float4 pb = *reinterpret_cast<const float4*>(PB + col0);
    #pragma unroll
    for (int rr = 0; rr < 8; rr++) {
        int b = 8*ty + rr;
        float4 v;
        v.x = foldp(acc[rr][0]) + pb.x;
        v.y = foldp(acc[rr][1]) + pb.y;
        v.z = foldp(acc[rr][2]) + pb.z;
        v.w = foldp(acc[rr][3]) + pb.w;
        *reinterpret_cast<float4*>(lout + ((size_t)b * TT + t) * VV + col0) = v;
        ULL key = mkkey(v.x, col0);
        ULL k2  = mkkey(v.y, col0 + 1); if (k2 > key) key = k2;
        k2      = mkkey(v.z, col0 + 2); if (k2 > key) key = k2;
        k2      = mkkey(v.w, col0 + 3); if (k2 > key) key = k2;
        #pragma unroll
        for (int off = 16; off > 0; off >>= 1) {
            ULL o = __shfl_xor_sync(0xFFFFFFFFu, key, off);
            if (o > key) key = o;
        }
        if (tx == 0) atomicMax(&g_keys[t * B_ + b], key);
    }
}

// ---------------- 6) finalize preds ----------------
__global__ void preds_kernel(float* __restrict__ out) {
    int i = blockIdx.x * 256 + threadIdx.x;
    if (i >= TT * B_) return;
    ULL k = g_keys[i];
    unsigned col = 0xFFFFFFFFu - (unsigned)(k & 0xFFFFFFFFull);
    int t = i >> 6, b = i & 63;
    out[b * TT + t] = (float)col;
}

// ---------------- launch ----------------
extern "C" void kernel_launch(void* const* d_in, const int* in_sizes, int n_in,
                              void* d_out, int out_size) {
    const int*   ids    = (const int*)  d_in[0];
    const float* istate = (const float*)d_in[1];
    const float* emb    = (const float*)d_in[2];
    const float* encW   = (const float*)d_in[3];
    const float* Wih0   = (const float*)d_in[4];
    const float* Whh0   = (const float*)d_in[5];
    const float* bih0   = (const float*)d_in[6];
    const float* bhh0   = (const float*)d_in[7];
    const float* Wih1   = (const float*)d_in[8];
    const float* Whh1   = (const float*)d_in[9];
    const float* bih1   = (const float*)d_in[10];
    const float* bhh1   = (const float*)d_in[11];
    const float* PW     = (const float*)d_in[12];
    const float* PB     = (const float*)d_in[13];
    float* out = (float*)d_out;

    pack_kernel<<<(G4 * 2048) / 256, 256>>>(Wih0, Whh0, Wih1, Whh1, bih0, bhh0, bih1, bhh1);
    h0init_kernel<<<32, 128>>>(istate, encW);
    embx_kernel<<<dim3(TT, 32), 256>>>(ids, emb);
    for (int t = 0; t < TT; t++) {
        cell_kernel<<<128, 256>>>(t, 0);
        cell_kernel<<<128, 256>>>(t, 1);
    }
    proj_kernel<<<dim3(TT, 250), 256>>>(PW, PB, out);
    preds_kernel<<<16, 256>>>(out);
}

// round 7
// speedup vs baseline: 1.1658x; 1.0023x over previous
#include <cuda_runtime.h>
#include <math.h>

typedef unsigned long long ULL;
typedef unsigned int uint;

// ---------------- constants ----------------
#define B_   64
#define TT   63          // time steps actually computed (T-1)
#define EE   512
#define HH   1024
#define VV   32000
#define G4   4096        // 4*H

// ---------------- scratch (device globals; no allocation) ----------------
__device__ float g_Wih0p[G4 * EE];          //  8.4 MB  gate-interleaved W_ih0
__device__ float g_Whh0p[G4 * HH];          // 16.8 MB  gate-interleaved W_hh0
__device__ float g_W1cat[G4 * 2 * HH];      // 33.6 MB  [W_ih1 | W_hh1] interleaved
__device__ float g_b0p[G4];
__device__ float g_b1p[G4];
__device__ float g_G0x[TT * B_ * G4];       // 66 MB    x-side layer0 gates (+bias)
__device__ float g_H1 [TT * B_ * HH];       // 16.5 MB  h1 per step
__device__ float g_h0buf[2][B_ * HH];
__device__ float g_h1buf[2][B_ * HH];
__device__ float g_c0s[B_ * HH];
__device__ float g_c1s[B_ * HH];
__device__ ULL   g_keys[TT * B_];           // packed argmax keys, indexed t*64+b

// ---------------- helpers ----------------
static __device__ __forceinline__ void fma2(ULL& acc, ULL a, ULL b) {
    asm("fma.rn.f32x2 %0, %1, %2, %0;" : "+l"(acc) : "l"(a), "l"(b));
}
static __device__ __forceinline__ ULL mk2(float x, float y) {
    ULL r;
    asm("mov.b64 %0, {%1, %2};" : "=l"(r)
        : "r"(__float_as_uint(x)), "r"(__float_as_uint(y)));
    return r;
}
static __device__ __forceinline__ float selh(ULL u, int hi) {
    return __uint_as_float(hi ? (unsigned)(u >> 32) : (unsigned)u);
}
static __device__ __forceinline__ float foldp(ULL u) {   // even-k part + odd-k part
    return selh(u, 0) + selh(u, 1);
}
static __device__ __forceinline__ ULL dup2(float b) {
    ULL r; unsigned u = __float_as_uint(b);
    asm("mov.b64 %0, {%1, %1};" : "=l"(r) : "r"(u));
    return r;
}
static __device__ __forceinline__ float sigf(float x) { return 1.0f / (1.0f + expf(-x)); }
static __device__ __forceinline__ unsigned fordu(float v) {
    unsigned u = __float_as_uint(v);
    return u ^ (((int)u >> 31) | 0x80000000u);
}
static __device__ __forceinline__ ULL mkkey(float v, int col) {
    return ((ULL)fordu(v) << 32) | (ULL)(0xFFFFFFFFu - (unsigned)col);
}

// ---------------- 1) pack / init ----------------
__global__ void pack_kernel(const float* __restrict__ Wih0, const float* __restrict__ Whh0,
                            const float* __restrict__ Wih1, const float* __restrict__ Whh1,
                            const float* __restrict__ bih0, const float* __restrict__ bhh0,
                            const float* __restrict__ bih1, const float* __restrict__ bhh1) {
    int i = blockIdx.x * 256 + threadIdx.x;           // covers 4096*2048
    if (i < TT * B_) g_keys[i] = 0ull;
    int rp  = i >> 11;                                // new (interleaved) row
    int k   = i & 2047;
    int old = ((rp & 3) << 10) + (rp >> 2);           // gate*1024 + hidden
    g_W1cat[i] = (k < HH) ? Wih1[old * HH + k] : Whh1[old * HH + (k - HH)];
    if (k < EE) g_Wih0p[rp * EE + k] = Wih0[old * EE + k];
    if (k < HH) g_Whh0p[rp * HH + k] = Whh0[old * HH + k];
    if (k == 0) {
        g_b0p[rp] = bih0[old] + bhh0[old];
        g_b1p[rp] = bih1[old] + bhh1[old];
    }
}

// ---------------- 2) h0 = initial_state @ enc_proj_W^T  (also c0,h1,c1) ----------------
// small one-time kernel (kept from R2, known-correct)
__global__ __launch_bounds__(128) void h0init_kernel(const float* __restrict__ S,
                                                     const float* __restrict__ EW) {
    __shared__ float A_sm[32 * 66];
    __shared__ float B_sm[32 * 36];
    int tid = threadIdx.x, tr = tid >> 3, tc = tid & 7;
    int cb = blockIdx.x * 32;
    ULL acc[2][4] = {{0,0,0,0},{0,0,0,0}};
    float pA[16], pB[8];
    #pragma unroll
    for (int e = 0; e < 16; e++) { int idx = e*128+tid; pA[e] = S[(idx>>5)*2048 + (idx&31)]; }
    #pragma unroll
    for (int e = 0; e < 8;  e++) { int idx = e*128+tid; pB[e] = EW[(size_t)(cb+(idx>>5))*2048 + (idx&31)]; }
    for (int k0 = 0; k0 < 2048; k0 += 32) {
        __syncthreads();
        #pragma unroll
        for (int e = 0; e < 16; e++) { int idx = e*128+tid; A_sm[(idx&31)*66 + (idx>>5)] = pA[e]; }
        #pragma unroll
        for (int e = 0; e < 8;  e++) { int idx = e*128+tid; B_sm[(idx&31)*36 + (idx>>5)] = pB[e]; }
        __syncthreads();
        int kn = k0 + 32;
        if (kn < 2048) {
            #pragma unroll
            for (int e = 0; e < 16; e++) { int idx = e*128+tid; pA[e] = S[(idx>>5)*2048 + kn + (idx&31)]; }
            #pragma unroll
            for (int e = 0; e < 8;  e++) { int idx = e*128+tid; pB[e] = EW[(size_t)(cb+(idx>>5))*2048 + kn + (idx&31)]; }
        }
        #pragma unroll 8
        for (int kk = 0; kk < 32; kk++) {
            const ULL* ar = reinterpret_cast<const ULL*>(A_sm + kk * 66);
            ULL a0 = ar[2*tr], a1 = ar[2*tr+1];
            float4 bv = *reinterpret_cast<const float4*>(B_sm + kk*36 + 4*tc);
            ULL b0 = dup2(bv.x), b1 = dup2(bv.y), b2 = dup2(bv.z), b3 = dup2(bv.w);
            fma2(acc[0][0], a0, b0); fma2(acc[1][0], a1, b0);
            fma2(acc[0][1], a0, b1); fma2(acc[1][1], a1, b1);
            fma2(acc[0][2], a0, b2); fma2(acc[1][2], a1, b2);
            fma2(acc[0][3], a0, b3); fma2(acc[1][3], a1, b3);
        }
    }
    #pragma unroll
    for (int p = 0; p < 2; p++) {
        #pragma unroll
        for (int hi = 0; hi < 2; hi++) {
            int r = 4*tr + 2*p + hi;
            #pragma unroll
            for (int c = 0; c < 4; c++) {
                int col = cb + 4*tc + c;
                float v = selh(acc[p][c], hi);
                g_h0buf[0][r*HH + col] = v;
                g_c0s   [r*HH + col]   = v;
                g_h1buf[0][r*HH + col] = v;
                g_c1s   [r*HH + col]   = v;
            }
        }
    }
}

// ==================================================================================
// k-pair GEMM kernels: acc pairs are (sum over even k, sum over odd k); no operand
// duplication; A read via warp-broadcast ulonglong2; XOR swizzle for 2-wf STS.
// ==================================================================================

// ---------------- 3) G0x = emb[ids] @ Wih0p^T + b0p ----------------
// tile 64x128, 256 threads, grid (63, 32), K=512, K-block=32 (16 kp)
__global__ __launch_bounds__(256) void embx_kernel(const int* __restrict__ ids,
                                                   const float* __restrict__ emb) {
    __shared__ ULL A2[16 * 64];    // [kp][row^swz]  8 KB
    __shared__ ULL B2[16 * 128];   // [kp][col^swz] 16 KB
    __shared__ int ids_sm[B_];
    int tid = threadIdx.x, ty = tid >> 5, tx = tid & 31;
    int t = blockIdx.x, cb = blockIdx.y * 128;
    if (tid < B_) ids_sm[tid] = ids[tid * 64 + t];
    __syncthreads();

    ULL acc[8][4];
    #pragma unroll
    for (int r = 0; r < 8; r++)
        #pragma unroll
        for (int c = 0; c < 4; c++) acc[r][c] = 0ull;

    int lkp = tid & 15;            // load kp
    int lr  = tid >> 4;            // 0..15
    int lsw = (lkp << 1) & 30;
    uint aG[4];
    #pragma unroll
    for (int e = 0; e < 4; e++) aG[e] = (uint)ids_sm[lr + 16*e] * EE + 2*lkp;
    uint bG = (uint)(cb + lr) * EE + 2*lkp;     // + 16e*EE

    float2 pA[4], pB[8];
    #pragma unroll
    for (int e = 0; e < 4; e++) pA[e] = *reinterpret_cast<const float2*>(emb + aG[e]);
    #pragma unroll
    for (int e = 0; e < 8; e++) pB[e] = *reinterpret_cast<const float2*>(g_Wih0p + bG + (uint)(16*e)*EE);

    for (int k0 = 0; k0 < EE; k0 += 32) {
        __syncthreads();
        #pragma unroll
        for (int e = 0; e < 4; e++) A2[lkp*64  + ((lr + 16*e) ^ lsw)] = *reinterpret_cast<ULL*>(&pA[e]);
        #pragma unroll
        for (int e = 0; e < 8; e++) B2[lkp*128 + ((lr + 16*e) ^ lsw)] = *reinterpret_cast<ULL*>(&pB[e]);
        __syncthreads();
        int kn = k0 + 32;
        if (kn < EE) {
            #pragma unroll
            for (int e = 0; e < 4; e++) pA[e] = *reinterpret_cast<const float2*>(emb + aG[e] + kn);
            #pragma unroll
            for (int e = 0; e < 8; e++) pB[e] = *reinterpret_cast<const float2*>(g_Wih0p + bG + kn + (uint)(16*e)*EE);
        }
        #pragma unroll
        for (int kp = 0; kp < 16; kp++) {
            int s = (kp << 1) & 30;
            ulonglong2 bv0 = *reinterpret_cast<const ulonglong2*>(&B2[kp*128 + ((4*tx) ^ s)]);
            ulonglong2 bv1 = *reinterpret_cast<const ulonglong2*>(&B2[kp*128 + ((4*tx + 2) ^ s)]);
            #pragma unroll
            for (int j = 0; j < 4; j++) {
                ulonglong2 av = *reinterpret_cast<const ulonglong2*>(&A2[kp*64 + ((8*ty + 2*j) ^ s)]);
                fma2(acc[2*j][0],   av.x, bv0.x); fma2(acc[2*j][1],   av.x, bv0.y);
                fma2(acc[2*j][2],   av.x, bv1.x); fma2(acc[2*j][3],   av.x, bv1.y);
                fma2(acc[2*j+1][0], av.y, bv0.x); fma2(acc[2*j+1][1], av.y, bv0.y);
                fma2(acc[2*j+1][2], av.y, bv1.x); fma2(acc[2*j+1][3], av.y, bv1.y);
            }
        }
    }
    float* outp = g_G0x + (size_t)(t * B_) * G4;
    int col0 = cb + 4*tx;
    float4 bb = *reinterpret_cast<const float4*>(g_b0p + col0);
    #pragma unroll
    for (int rr = 0; rr < 8; rr++) {
        int row = 8*ty + rr;
        float4 v;
        v.x = foldp(acc[rr][0]) + bb.x;
        v.y = foldp(acc[rr][1]) + bb.y;
        v.z = foldp(acc[rr][2]) + bb.z;
        v.w = foldp(acc[rr][3]) + bb.w;
        *reinterpret_cast<float4*>(outp + (size_t)row*G4 + col0) = v;
    }
}

// ---------------- 4) fused LSTM cell step (one layer) ----------------
// tile 64x32 gate-cols, 256 threads, grid 128, K-block=64 (32 kp), double-buffered
__global__ __launch_bounds__(256) void cell_kernel(int t, int layer) {
    __shared__ ULL A2[2][32 * 64];   // 2 x 16 KB
    __shared__ ULL B2[2][32 * 32];   // 2 x  8 KB
    int tid = threadIdx.x;
    int w  = tid >> 5, l = tid & 31;
    int rp = l >> 3;                 // 0..3 -> rows 8w+2rp, +1
    int cg = l & 7;                  // 4 cols at 4cg
    int cb = blockIdx.x * 32;
    int in = t & 1, out = in ^ 1;

    const float *A1, *A2g, *W;
    float *cst, *hout, *hcopy = nullptr;
    int K;
    if (layer == 0) {
        A1 = g_h0buf[in]; A2g = A1; W = g_Whh0p; K = HH;
        cst = g_c0s; hout = g_h0buf[out];
    } else {
        A1 = g_h0buf[out]; A2g = g_h1buf[in]; W = g_W1cat; K = 2 * HH;
        cst = g_c1s; hout = g_h1buf[out];
        hcopy = g_H1 + (size_t)(t * B_) * HH;
    }

    int r0 = 8*w + 2*rp;
    int gc0 = cb + 4*cg;
    ULL acc[2][4];
    if (layer == 0) {
        const float* initp = g_G0x + (size_t)(t * B_) * G4;
        float4 i0 = *reinterpret_cast<const float4*>(initp + (size_t)r0     * G4 + gc0);
        float4 i1 = *reinterpret_cast<const float4*>(initp + (size_t)(r0+1) * G4 + gc0);
        acc[0][0] = mk2(i0.x, 0.f); acc[0][1] = mk2(i0.y, 0.f);
        acc[0][2] = mk2(i0.z, 0.f); acc[0][3] = mk2(i0.w, 0.f);
        acc[1][0] = mk2(i1.x, 0.f); acc[1][1] = mk2(i1.y, 0.f);
        acc[1][2] = mk2(i1.z, 0.f); acc[1][3] = mk2(i1.w, 0.f);
    } else {
        float4 bb = *reinterpret_cast<const float4*>(g_b1p + gc0);
        acc[0][0] = mk2(bb.x, 0.f); acc[0][1] = mk2(bb.y, 0.f);
        acc[0][2] = mk2(bb.z, 0.f); acc[0][3] = mk2(bb.w, 0.f);
        acc[1][0] = acc[0][0]; acc[1][1] = acc[0][1];
        acc[1][2] = acc[0][2]; acc[1][3] = acc[0][3];
    }

    // load mapping: kp = tid&31, A rows = (tid>>5)+8e (e<8), B cols = (tid>>5)+8e (e<4)
    int lkp = l;                        // within warp kp == lane? no: kp = tid&31 == l
    int lsw = (lkp & 15) << 1;
    uint aBase = (uint)w * HH + 2*lkp;            // row w+8e -> + 8e*HH
    uint bBase = (uint)(cb + w) * K + 2*lkp;      // col w+8e -> + 8e*K

    int nb = K >> 6;
    float2 pA[8], pB[4];
    // block 0 load + store
    #pragma unroll
    for (int e = 0; e < 8; e++) pA[e] = *reinterpret_cast<const float2*>(A1 + aBase + (uint)(8*e)*HH);
    #pragma unroll
    for (int e = 0; e < 4; e++) pB[e] = *reinterpret_cast<const float2*>(W  + bBase + (uint)(8*e)*K);
    #pragma unroll
    for (int e = 0; e < 8; e++) A2[0][lkp*64 + ((w + 8*e) ^ lsw)] = *reinterpret_cast<ULL*>(&pA[e]);
    #pragma unroll
    for (int e = 0; e < 4; e++) B2[0][lkp*32 + ((w + 8*e) ^ lsw)] = *reinterpret_cast<ULL*>(&pB[e]);
    // block 1 loads into regs
    if (nb > 1) {
        const float* Asrc = (64 < HH) ? (A1 + 64) : (A2g + (64 - HH));
        #pragma unroll
        for (int e = 0; e < 8; e++) pA[e] = *reinterpret_cast<const float2*>(Asrc + aBase + (uint)(8*e)*HH);
        #pragma unroll
        for (int e = 0; e < 4; e++) pB[e] = *reinterpret_cast<const float2*>(W + bBase + 64 + (uint)(8*e)*K);
    }

    for (int blk = 0; blk < nb; blk++) {
        __syncthreads();
        int cur = blk & 1, nxt = cur ^ 1;
        if (blk + 1 < nb) {
            #pragma unroll
            for (int e = 0; e < 8; e++) A2[nxt][lkp*64 + ((w + 8*e) ^ lsw)] = *reinterpret_cast<ULL*>(&pA[e]);
            #pragma unroll
            for (int e = 0; e < 4; e++) B2[nxt][lkp*32 + ((w + 8*e) ^ lsw)] = *reinterpret_cast<ULL*>(&pB[e]);
            if (blk + 2 < nb) {
                int k0 = (blk + 2) << 6;
                const float* Asrc = (k0 < HH) ? (A1 + k0) : (A2g + (k0 - HH));
                #pragma unroll
                for (int e = 0; e < 8; e++) pA[e] = *reinterpret_cast<const float2*>(Asrc + aBase + (uint)(8*e)*HH);
                #pragma unroll
                for (int e = 0; e < 4; e++) pB[e] = *reinterpret_cast<const float2*>(W + bBase + k0 + (uint)(8*e)*K);
            }
        }
        const ULL* Ab = A2[cur];
        const ULL* Bb = B2[cur];
        #pragma unroll
        for (int kp = 0; kp < 32; kp++) {
            int s = (kp & 15) << 1;
            ulonglong2 av  = *reinterpret_cast<const ulonglong2*>(&Ab[kp*64 + (r0 ^ s)]);
            ulonglong2 bv0 = *reinterpret_cast<const ulonglong2*>(&Bb[kp*32 + ((4*cg) ^ s)]);
            ulonglong2 bv1 = *reinterpret_cast<const ulonglong2*>(&Bb[kp*32 + ((4*cg + 2) ^ s)]);
            fma2(acc[0][0], av.x, bv0.x); fma2(acc[0][1], av.x, bv0.y);
            fma2(acc[0][2], av.x, bv1.x); fma2(acc[0][3], av.x, bv1.y);
            fma2(acc[1][0], av.y, bv0.x); fma2(acc[1][1], av.y, bv0.y);
            fma2(acc[1][2], av.y, bv1.x); fma2(acc[1][3], av.y, bv1.y);
        }
    }

    // fused LSTM activation epilogue (thread owns gates i,f,g,o of hidden j, rows r0,r0+1)
    int j = (cb >> 2) + cg;
    #pragma unroll
    for (int r = 0; r < 2; r++) {
        int row = r0 + r;
        float iv = foldp(acc[r][0]);
        float fv = foldp(acc[r][1]);
        float gv = foldp(acc[r][2]);
        float ov = foldp(acc[r][3]);
        float cold = cst[row*HH + j];
        float cn = sigf(fv) * cold + sigf(iv) * tanhf(gv);
        float h  = sigf(ov) * tanhf(cn);
        cst [row*HH + j] = cn;
        hout[row*HH + j] = h;
        if (hcopy) hcopy[row*HH + j] = h;
    }
}

// ---------------- 5) logits = H1 @ proj_W^T + b, fused argmax ----------------
// tile 64x128, 256 threads, grid (63, 250), K=1024, K-block=32 (16 kp)
__global__ __launch_bounds__(256) void proj_kernel(const float* __restrict__ PW,
                                                   const float* __restrict__ PB,
                                                   float* __restrict__ out) {
    __shared__ ULL A2[16 * 64];    //  8 KB
    __shared__ ULL B2[16 * 128];   // 16 KB
    int tid = threadIdx.x, ty = tid >> 5, tx = tid & 31;
    int t = blockIdx.x, cb = blockIdx.y * 128;
    const float* A = g_H1 + (size_t)(t * B_) * HH;

    ULL acc[8][4];
    #pragma unroll
    for (int r = 0; r < 8; r++)
        #pragma unroll
        for (int c = 0; c < 4; c++) acc[r][c] = 0ull;

    int lkp = tid & 15;
    int lr  = tid >> 4;
    int lsw = (lkp << 1) & 30;
    uint aBase = (uint)lr * HH + 2*lkp;            // + 16e*HH
    uint bBase = (uint)(cb + lr) * HH + 2*lkp;     // + 16e*HH

    float2 pA[4], pB[8];
    #pragma unroll
    for (int e = 0; e < 4; e++) pA[e] = *reinterpret_cast<const float2*>(A  + aBase + (uint)(16*e)*HH);
    #pragma unroll
    for (int e = 0; e < 8; e++) pB[e] = *reinterpret_cast<const float2*>(PW + bBase + (uint)(16*e)*HH);

    for (int k0 = 0; k0 < HH; k0 += 32) {
        __syncthreads();
        #pragma unroll
        for (int e = 0; e < 4; e++) A2[lkp*64  + ((lr + 16*e) ^ lsw)] = *reinterpret_cast<ULL*>(&pA[e]);
        #pragma unroll
        for (int e = 0; e < 8; e++) B2[lkp*128 + ((lr + 16*e) ^ lsw)] = *reinterpret_cast<ULL*>(&pB[e]);
        __syncthreads();
        int kn = k0 + 32;
        if (kn < HH) {
            #pragma unroll
            for (int e = 0; e < 4; e++) pA[e] = *reinterpret_cast<const float2*>(A  + aBase + kn + (uint)(16*e)*HH);
            #pragma unroll
            for (int e = 0; e < 8; e++) pB[e] = *reinterpret_cast<const float2*>(PW + bBase + kn + (uint)(16*e)*HH);
        }
        #pragma unroll
        for (int kp = 0; kp < 16; kp++) {
            int s = (kp << 1) & 30;
            ulonglong2 bv0 = *reinterpret_cast<const ulonglong2*>(&B2[kp*128 + ((4*tx) ^ s)]);
            ulonglong2 bv1 = *reinterpret_cast<const ulonglong2*>(&B2[kp*128 + ((4*tx + 2) ^ s)]);
            #pragma unroll
            for (int j = 0; j < 4; j++) {
                ulonglong2 av = *reinterpret_cast<const ulonglong2*>(&A2[kp*64 + ((8*ty + 2*j) ^ s)]);
                fma2(acc[2*j][0],   av.x, bv0.x); fma2(acc[2*j][1],   av.x, bv0.y);
                fma2(acc[2*j][2],   av.x, bv1.x); fma2(acc[2*j][3],   av.x, bv1.y);
                fma2(acc[2*j+1][0], av.y, bv0.x); fma2(acc[2*j+1][1], av.y, bv0.y);
                fma2(acc[2*j+1][2], av.y, bv1.x); fma2(acc[2*j+1][3], av.y, bv1.y);
            }
        }
    }

    float* lout = out + TT * B_;                 // logits after preds
    int col0 = cb + 4*tx;
    float4 pb = *reinterpret_cast<const float4*>(PB + col0);
    #pragma unroll
    for (int rr = 0; rr < 8; rr++) {
        int b = 8*ty + rr;
        float4 v;
        v.x = foldp(acc[rr][0]) + pb.x;
        v.y = foldp(acc[rr][1]) + pb.y;
        v.z = foldp(acc[rr][2]) + pb.z;
        v.w = foldp(acc[rr][3]) + pb.w;
        *reinterpret_cast<float4*>(lout + ((size_t)b * TT + t) * VV + col0) = v;
        ULL key = mkkey(v.x, col0);
        ULL k2  = mkkey(v.y, col0 + 1); if (k2 > key) key = k2;
        k2      = mkkey(v.z, col0 + 2); if (k2 > key) key = k2;
        k2      = mkkey(v.w, col0 + 3); if (k2 > key) key = k2;
        #pragma unroll
        for (int off = 16; off > 0; off >>= 1) {
            ULL o = __shfl_xor_sync(0xFFFFFFFFu, key, off);
            if (o > key) key = o;
        }
        if (tx == 0) atomicMax(&g_keys[t * B_ + b], key);
    }
}

// ---------------- 6) finalize preds ----------------
__global__ void preds_kernel(float* __restrict__ out) {
    int i = blockIdx.x * 256 + threadIdx.x;
    if (i >= TT * B_) return;
    ULL k = g_keys[i];
    unsigned col = 0xFFFFFFFFu - (unsigned)(k & 0xFFFFFFFFull);
    int t = i >> 6, b = i & 63;
    out[b * TT + t] = (float)col;
}

// ---------------- launch ----------------
extern "C" void kernel_launch(void* const* d_in, const int* in_sizes, int n_in,
                              void* d_out, int out_size) {
    const int*   ids    = (const int*)  d_in[0];
    const float* istate = (const float*)d_in[1];
    const float* emb    = (const float*)d_in[2];
    const float* encW   = (const float*)d_in[3];
    const float* Wih0   = (const float*)d_in[4];
    const float* Whh0   = (const float*)d_in[5];
    const float* bih0   = (const float*)d_in[6];
    const float* bhh0   = (const float*)d_in[7];
    const float* Wih1   = (const float*)d_in[8];
    const float* Whh1   = (const float*)d_in[9];
    const float* bih1   = (const float*)d_in[10];
    const float* bhh1   = (const float*)d_in[11];
    const float* PW     = (const float*)d_in[12];
    const float* PB     = (const float*)d_in[13];
    float* out = (float*)d_out;

    pack_kernel<<<(G4 * 2048) / 256, 256>>>(Wih0, Whh0, Wih1, Whh1, bih0, bhh0, bih1, bhh1);
    h0init_kernel<<<32, 128>>>(istate, encW);
    embx_kernel<<<dim3(TT, 32), 256>>>(ids, emb);
    for (int t = 0; t < TT; t++) {
        cell_kernel<<<128, 256>>>(t, 0);
        cell_kernel<<<128, 256>>>(t, 1);
    }
    proj_kernel<<<dim3(TT, 250), 256>>>(PW, PB, out);
    preds_kernel<<<16, 256>>>(out);
}

// round 8
// speedup vs baseline: 1.6189x; 1.3887x over previous
#include <cuda_runtime.h>
#include <math.h>

typedef unsigned long long ULL;
typedef unsigned int uint;

// ---------------- constants ----------------
#define B_   64
#define TT   63          // time steps actually computed (T-1)
#define EE   512
#define HH   1024
#define VV   32000
#define G4   4096        // 4*H

// ---------------- scratch (device globals; no allocation) ----------------
__device__ float g_Wih0p[G4 * EE];          //  8.4 MB  gate-interleaved W_ih0
__device__ float g_Whh0p[G4 * HH];          // 16.8 MB  gate-interleaved W_hh0
__device__ float g_W1cat[G4 * 2 * HH];      // 33.6 MB  [W_ih1 | W_hh1] interleaved
__device__ float g_b0p[G4];
__device__ float g_b1p[G4];
__device__ float g_G0x[TT * B_ * G4];       // 66 MB    x-side layer0 gates (+bias)
__device__ float g_H1 [TT * B_ * HH];       // 16.5 MB  h1 per step
__device__ float g_h0buf[2][B_ * HH];
__device__ float g_h1buf[2][B_ * HH];
__device__ float g_c0s[B_ * HH];
__device__ float g_c1s[B_ * HH];
__device__ ULL   g_keys[TT * B_];           // packed argmax keys, indexed t*64+b

// ---------------- helpers ----------------
static __device__ __forceinline__ void fma2(ULL& acc, ULL a, ULL b) {
    asm("fma.rn.f32x2 %0, %1, %2, %0;" : "+l"(acc) : "l"(a), "l"(b));
}
static __device__ __forceinline__ ULL mk2(float x, float y) {
    ULL r;
    asm("mov.b64 %0, {%1, %2};" : "=l"(r)
        : "r"(__float_as_uint(x)), "r"(__float_as_uint(y)));
    return r;
}
static __device__ __forceinline__ float selh(ULL u, int hi) {
    return __uint_as_float(hi ? (unsigned)(u >> 32) : (unsigned)u);
}
static __device__ __forceinline__ float foldp(ULL u) {   // even-k part + odd-k part
    return selh(u, 0) + selh(u, 1);
}
static __device__ __forceinline__ ULL dup2(float b) {
    ULL r; unsigned u = __float_as_uint(b);
    asm("mov.b64 %0, {%1, %1};" : "=l"(r) : "r"(u));
    return r;
}
static __device__ __forceinline__ float sigf(float x) { return 1.0f / (1.0f + expf(-x)); }
static __device__ __forceinline__ unsigned fordu(float v) {
    unsigned u = __float_as_uint(v);
    return u ^ (((int)u >> 31) | 0x80000000u);
}
static __device__ __forceinline__ ULL mkkey(float v, int col) {
    return ((ULL)fordu(v) << 32) | (ULL)(0xFFFFFFFFu - (unsigned)col);
}
// bank-spreading B entry index: col -> col + 2*(col/16)
static __device__ __forceinline__ int bcol(int c) { return c + ((c >> 4) << 1); }

// ---------------- 1) pack / init ----------------
__global__ void pack_kernel(const float* __restrict__ Wih0, const float* __restrict__ Whh0,
                            const float* __restrict__ Wih1, const float* __restrict__ Whh1,
                            const float* __restrict__ bih0, const float* __restrict__ bhh0,
                            const float* __restrict__ bih1, const float* __restrict__ bhh1) {
    int i = blockIdx.x * 256 + threadIdx.x;           // covers 4096*2048
    if (i < TT * B_) g_keys[i] = 0ull;
    int rp  = i >> 11;                                // new (interleaved) row
    int k   = i & 2047;
    int old = ((rp & 3) << 10) + (rp >> 2);           // gate*1024 + hidden
    g_W1cat[i] = (k < HH) ? Wih1[old * HH + k] : Whh1[old * HH + (k - HH)];
    if (k < EE) g_Wih0p[rp * EE + k] = Wih0[old * EE + k];
    if (k < HH) g_Whh0p[rp * HH + k] = Whh0[old * HH + k];
    if (k == 0) {
        g_b0p[rp] = bih0[old] + bhh0[old];
        g_b1p[rp] = bih1[old] + bhh1[old];
    }
}

// ---------------- 2) h0 = initial_state @ enc_proj_W^T  (also c0,h1,c1) ----------------
// small one-time kernel (known-correct since R2)
__global__ __launch_bounds__(128) void h0init_kernel(const float* __restrict__ S,
                                                     const float* __restrict__ EW) {
    __shared__ float A_sm[32 * 66];
    __shared__ float B_sm[32 * 36];
    int tid = threadIdx.x, tr = tid >> 3, tc = tid & 7;
    int cb = blockIdx.x * 32;
    ULL acc[2][4] = {{0,0,0,0},{0,0,0,0}};
    float pA[16], pB[8];
    #pragma unroll
    for (int e = 0; e < 16; e++) { int idx = e*128+tid; pA[e] = S[(idx>>5)*2048 + (idx&31)]; }
    #pragma unroll
    for (int e = 0; e < 8;  e++) { int idx = e*128+tid; pB[e] = EW[(size_t)(cb+(idx>>5))*2048 + (idx&31)]; }
    for (int k0 = 0; k0 < 2048; k0 += 32) {
        __syncthreads();
        #pragma unroll
        for (int e = 0; e < 16; e++) { int idx = e*128+tid; A_sm[(idx&31)*66 + (idx>>5)] = pA[e]; }
        #pragma unroll
        for (int e = 0; e < 8;  e++) { int idx = e*128+tid; B_sm[(idx&31)*36 + (idx>>5)] = pB[e]; }
        __syncthreads();
        int kn = k0 + 32;
        if (kn < 2048) {
            #pragma unroll
            for (int e = 0; e < 16; e++) { int idx = e*128+tid; pA[e] = S[(idx>>5)*2048 + kn + (idx&31)]; }
            #pragma unroll
            for (int e = 0; e < 8;  e++) { int idx = e*128+tid; pB[e] = EW[(size_t)(cb+(idx>>5))*2048 + kn + (idx&31)]; }
        }
        #pragma unroll 8
        for (int kk = 0; kk < 32; kk++) {
            const ULL* ar = reinterpret_cast<const ULL*>(A_sm + kk * 66);
            ULL a0 = ar[2*tr], a1 = ar[2*tr+1];
            float4 bv = *reinterpret_cast<const float4*>(B_sm + kk*36 + 4*tc);
            ULL b0 = dup2(bv.x), b1 = dup2(bv.y), b2 = dup2(bv.z), b3 = dup2(bv.w);
            fma2(acc[0][0], a0, b0); fma2(acc[1][0], a1, b0);
            fma2(acc[0][1], a0, b1); fma2(acc[1][1], a1, b1);
            fma2(acc[0][2], a0, b2); fma2(acc[1][2], a1, b2);
            fma2(acc[0][3], a0, b3); fma2(acc[1][3], a1, b3);
        }
    }
    #pragma unroll
    for (int p = 0; p < 2; p++) {
        #pragma unroll
        for (int hi = 0; hi < 2; hi++) {
            int r = 4*tr + 2*p + hi;
            #pragma unroll
            for (int c = 0; c < 4; c++) {
                int col = cb + 4*tc + c;
                float v = selh(acc[p][c], hi);
                g_h0buf[0][r*HH + col] = v;
                g_c0s   [r*HH + col]   = v;
                g_h1buf[0][r*HH + col] = v;
                g_c1s   [r*HH + col]   = v;
            }
        }
    }
}

// ==================================================================================
// Bank-exact k-pair GEMMs. A2[kp][row] stride 66 (ULL); B2[kp][bcol(col)] stride even.
// Compute: warp ty owns rows 8ty..8ty+7 (A broadcast reads), lane tx owns 4 cols.
// ==================================================================================

// ---------------- 3) G0x = emb[ids] @ Wih0p^T + b0p ----------------
// tile 64x128, 256 threads, 2 CTAs/SM, grid (63, 32), K=512, K-block 32
__global__ __launch_bounds__(256, 2) void embx_kernel(const int* __restrict__ ids,
                                                      const float* __restrict__ emb) {
    __shared__ ULL A2s[16 * 66];
    __shared__ ULL B2s[16 * 142];
    __shared__ int ids_sm[B_];
    int tid = threadIdx.x, ty = tid >> 5, tx = tid & 31;
    int t = blockIdx.x, cb = blockIdx.y * 128;
    if (tid < B_) ids_sm[tid] = ids[tid * 64 + t];
    __syncthreads();

    ULL acc[8][4];
    #pragma unroll
    for (int r = 0; r < 8; r++)
        #pragma unroll
        for (int c = 0; c < 4; c++) acc[r][c] = 0ull;

    int kp_l = tid & 15, lr = tid >> 4;     // fill roles
    uint aG[4];
    #pragma unroll
    for (int e = 0; e < 4; e++) aG[e] = (uint)ids_sm[lr + 16*e] * EE + 2*kp_l;
    uint bG = (uint)(cb + lr) * EE + 2*kp_l;          // + 16e*EE
    int aS = kp_l*66 + lr;                            // + 16e
    int bSb = kp_l*142;
    int bE[8];
    #pragma unroll
    for (int e = 0; e < 8; e++) bE[e] = bcol(lr + 16*e);

    int e0 = bcol(4*tx);
    int e1 = bcol(4*tx + 2);

    float2 pA[4], pB[8];
    #pragma unroll
    for (int e = 0; e < 4; e++) pA[e] = *reinterpret_cast<const float2*>(emb + aG[e]);
    #pragma unroll
    for (int e = 0; e < 8; e++) pB[e] = *reinterpret_cast<const float2*>(g_Wih0p + bG + (uint)(16*e)*EE);

    for (int k0 = 0; k0 < EE; k0 += 32) {
        __syncthreads();
        #pragma unroll
        for (int e = 0; e < 4; e++) A2s[aS + 16*e]  = *reinterpret_cast<ULL*>(&pA[e]);
        #pragma unroll
        for (int e = 0; e < 8; e++) B2s[bSb + bE[e]] = *reinterpret_cast<ULL*>(&pB[e]);
        __syncthreads();
        int kn = k0 + 32;
        if (kn < EE) {
            #pragma unroll
            for (int e = 0; e < 4; e++) pA[e] = *reinterpret_cast<const float2*>(emb + aG[e] + kn);
            #pragma unroll
            for (int e = 0; e < 8; e++) pB[e] = *reinterpret_cast<const float2*>(g_Wih0p + bG + kn + (uint)(16*e)*EE);
        }
        #pragma unroll
        for (int kp = 0; kp < 16; kp++) {
            ulonglong2 b0v = *reinterpret_cast<const ulonglong2*>(&B2s[kp*142 + e0]);
            ulonglong2 b1v = *reinterpret_cast<const ulonglong2*>(&B2s[kp*142 + e1]);
            #pragma unroll
            for (int j = 0; j < 4; j++) {
                ulonglong2 av = *reinterpret_cast<const ulonglong2*>(&A2s[kp*66 + 8*ty + 2*j]);
                fma2(acc[2*j  ][0], av.x, b0v.x); fma2(acc[2*j  ][1], av.x, b0v.y);
                fma2(acc[2*j  ][2], av.x, b1v.x); fma2(acc[2*j  ][3], av.x, b1v.y);
                fma2(acc[2*j+1][0], av.y, b0v.x); fma2(acc[2*j+1][1], av.y, b0v.y);
                fma2(acc[2*j+1][2], av.y, b1v.x); fma2(acc[2*j+1][3], av.y, b1v.y);
            }
        }
    }
    float* outp = g_G0x + (size_t)(t * B_) * G4;
    int col0 = cb + 4*tx;
    float4 bb = *reinterpret_cast<const float4*>(g_b0p + col0);
    #pragma unroll
    for (int rr = 0; rr < 8; rr++) {
        int row = 8*ty + rr;
        float4 v;
        v.x = foldp(acc[rr][0]) + bb.x;
        v.y = foldp(acc[rr][1]) + bb.y;
        v.z = foldp(acc[rr][2]) + bb.z;
        v.w = foldp(acc[rr][3]) + bb.w;
        *reinterpret_cast<float4*>(outp + (size_t)row*G4 + col0) = v;
    }
}

// ---------------- 4) fused LSTM cell step (one layer) ----------------
// tile 64x32 gate-cols, 256 threads, grid 128, K-block 32, double-buffered
__global__ __launch_bounds__(256) void cell_kernel(int t, int layer) {
    __shared__ ULL A2b[2][16 * 66];   // 2 x 8.4 KB
    __shared__ ULL B2b[2][16 * 34];   // 2 x 4.3 KB
    int tid = threadIdx.x;
    int w = tid >> 5, l = tid & 31;
    int r0 = 8*w + 2*(l >> 3);        // row pair
    int cg = l & 7;                   // 4 gate cols at 4cg
    int cb = blockIdx.x * 32;
    int in = t & 1, out = in ^ 1;

    const float *A1, *A2g, *W;
    float *cst, *hout, *hcopy = nullptr;
    int K;
    if (layer == 0) {
        A1 = g_h0buf[in]; A2g = A1; W = g_Whh0p; K = HH;
        cst = g_c0s; hout = g_h0buf[out];
    } else {
        A1 = g_h0buf[out]; A2g = g_h1buf[in]; W = g_W1cat; K = 2 * HH;
        cst = g_c1s; hout = g_h1buf[out];
        hcopy = g_H1 + (size_t)(t * B_) * HH;
    }

    int gc0 = cb + 4*cg;
    ULL acc[2][4];
    if (layer == 0) {
        const float* initp = g_G0x + (size_t)(t * B_) * G4;
        float4 i0 = *reinterpret_cast<const float4*>(initp + (size_t)r0     * G4 + gc0);
        float4 i1 = *reinterpret_cast<const float4*>(initp + (size_t)(r0+1) * G4 + gc0);
        acc[0][0] = mk2(i0.x, 0.f); acc[0][1] = mk2(i0.y, 0.f);
        acc[0][2] = mk2(i0.z, 0.f); acc[0][3] = mk2(i0.w, 0.f);
        acc[1][0] = mk2(i1.x, 0.f); acc[1][1] = mk2(i1.y, 0.f);
        acc[1][2] = mk2(i1.z, 0.f); acc[1][3] = mk2(i1.w, 0.f);
    } else {
        float4 bb = *reinterpret_cast<const float4*>(g_b1p + gc0);
        acc[0][0] = mk2(bb.x, 0.f); acc[0][1] = mk2(bb.y, 0.f);
        acc[0][2] = mk2(bb.z, 0.f); acc[0][3] = mk2(bb.w, 0.f);
        acc[1][0] = acc[0][0]; acc[1][1] = acc[0][1];
        acc[1][2] = acc[0][2]; acc[1][3] = acc[0][3];
    }

    // fill roles: kp = l&15, half = l>>4
    int kp_l = l & 15, half = l >> 4;
    int rowA = 2*w + half;                        // + 16e (e<4)
    int colB = w + 8*half;                        // + 16e (e<2)
    uint aBase = (uint)rowA * HH + 2*kp_l;
    uint bBase = (uint)(cb + colB) * K + 2*kp_l;
    int aS = kp_l*66 + rowA;                      // + 16e
    int bS0 = kp_l*34 + colB;                     // colB < 16 -> bcol = colB
    int bS1 = kp_l*34 + colB + 18;                // bcol(colB+16) = colB+18

    int e0 = 4*cg + ((cg >= 4) ? 2 : 0);
    int e1 = 4*cg + 2 + ((cg >= 4) ? 2 : 0);

    int nb = K >> 5;
    float2 pA[4], pB[2];
    // block 0: load + store
    #pragma unroll
    for (int e = 0; e < 4; e++) pA[e] = *reinterpret_cast<const float2*>(A1 + aBase + (uint)(16*e)*HH);
    pB[0] = *reinterpret_cast<const float2*>(W + bBase);
    pB[1] = *reinterpret_cast<const float2*>(W + bBase + (uint)16*K);
    #pragma unroll
    for (int e = 0; e < 4; e++) A2b[0][aS + 16*e] = *reinterpret_cast<ULL*>(&pA[e]);
    B2b[0][bS0] = *reinterpret_cast<ULL*>(&pB[0]);
    B2b[0][bS1] = *reinterpret_cast<ULL*>(&pB[1]);
    // block 1 loads into regs (k0=32 always inside A1)
    if (nb > 1) {
        #pragma unroll
        for (int e = 0; e < 4; e++) pA[e] = *reinterpret_cast<const float2*>(A1 + 32 + aBase + (uint)(16*e)*HH);
        pB[0] = *reinterpret_cast<const float2*>(W + bBase + 32);
        pB[1] = *reinterpret_cast<const float2*>(W + bBase + 32 + (uint)16*K);
    }

    for (int blk = 0; blk < nb; blk++) {
        __syncthreads();
        int cur = blk & 1, nxt = cur ^ 1;
        if (blk + 1 < nb) {
            #pragma unroll
            for (int e = 0; e < 4; e++) A2b[nxt][aS + 16*e] = *reinterpret_cast<ULL*>(&pA[e]);
            B2b[nxt][bS0] = *reinterpret_cast<ULL*>(&pB[0]);
            B2b[nxt][bS1] = *reinterpret_cast<ULL*>(&pB[1]);
            if (blk + 2 < nb) {
                int k0 = (blk + 2) << 5;
                const float* Asrc = (k0 < HH) ? (A1 + k0) : (A2g + (k0 - HH));
                #pragma unroll
                for (int e = 0; e < 4; e++) pA[e] = *reinterpret_cast<const float2*>(Asrc + aBase + (uint)(16*e)*HH);
                pB[0] = *reinterpret_cast<const float2*>(W + bBase + k0);
                pB[1] = *reinterpret_cast<const float2*>(W + bBase + k0 + (uint)16*K);
            }
        }
        const ULL* Ab = A2b[cur];
        const ULL* Bb = B2b[cur];
        #pragma unroll
        for (int kp = 0; kp < 16; kp++) {
            ulonglong2 av  = *reinterpret_cast<const ulonglong2*>(&Ab[kp*66 + r0]);
            ulonglong2 b0v = *reinterpret_cast<const ulonglong2*>(&Bb[kp*34 + e0]);
            ulonglong2 b1v = *reinterpret_cast<const ulonglong2*>(&Bb[kp*34 + e1]);
            fma2(acc[0][0], av.x, b0v.x); fma2(acc[0][1], av.x, b0v.y);
            fma2(acc[0][2], av.x, b1v.x); fma2(acc[0][3], av.x, b1v.y);
            fma2(acc[1][0], av.y, b0v.x); fma2(acc[1][1], av.y, b0v.y);
            fma2(acc[1][2], av.y, b1v.x); fma2(acc[1][3], av.y, b1v.y);
        }
    }

    // fused LSTM activation epilogue (thread owns gates i,f,g,o of hidden j)
    int j = (cb >> 2) + cg;
    #pragma unroll
    for (int r = 0; r < 2; r++) {
        int row = r0 + r;
        float iv = foldp(acc[r][0]);
        float fv = foldp(acc[r][1]);
        float gv = foldp(acc[r][2]);
        float ov = foldp(acc[r][3]);
        float cold = cst[row*HH + j];
        float cn = sigf(fv) * cold + sigf(iv) * tanhf(gv);
        float h  = sigf(ov) * tanhf(cn);
        cst [row*HH + j] = cn;
        hout[row*HH + j] = h;
        if (hcopy) hcopy[row*HH + j] = h;
    }
}

// ---------------- 5) logits = H1 @ proj_W^T + b, fused argmax ----------------
// tile 64x128, 256 threads, 2 CTAs/SM, grid (63, 250), K=1024, K-block 32
__global__ __launch_bounds__(256, 2) void proj_kernel(const float* __restrict__ PW,
                                                      const float* __restrict__ PB,
                                                      float* __restrict__ out) {
    __shared__ ULL A2s[16 * 66];
    __shared__ ULL B2s[16 * 142];
    int tid = threadIdx.x, ty = tid >> 5, tx = tid & 31;
    int t = blockIdx.x, cb = blockIdx.y * 128;
    const float* A = g_H1 + (size_t)(t * B_) * HH;

    ULL acc[8][4];
    #pragma unroll
    for (int r = 0; r < 8; r++)
        #pragma unroll
        for (int c = 0; c < 4; c++) acc[r][c] = 0ull;

    int kp_l = tid & 15, lr = tid >> 4;
    uint aBase = (uint)lr * HH + 2*kp_l;              // + 16e*HH (e<4)
    uint bBase = (uint)(cb + lr) * HH + 2*kp_l;       // + 16e*HH (e<8)
    int aS = kp_l*66 + lr;
    int bSb = kp_l*142;
    int bE[8];
    #pragma unroll
    for (int e = 0; e < 8; e++) bE[e] = bcol(lr + 16*e);

    int e0 = bcol(4*tx);
    int e1 = bcol(4*tx + 2);

    float2 pA[4], pB[8];
    #pragma unroll
    for (int e = 0; e < 4; e++) pA[e] = *reinterpret_cast<const float2*>(A  + aBase + (uint)(16*e)*HH);
    #pragma unroll
    for (int e = 0; e < 8; e++) pB[e] = *reinterpret_cast<const float2*>(PW + bBase + (uint)(16*e)*HH);

    for (int k0 = 0; k0 < HH; k0 += 32) {
        __syncthreads();
        #pragma unroll
        for (int e = 0; e < 4; e++) A2s[aS + 16*e]  = *reinterpret_cast<ULL*>(&pA[e]);
        #pragma unroll
        for (int e = 0; e < 8; e++) B2s[bSb + bE[e]] = *reinterpret_cast<ULL*>(&pB[e]);
        __syncthreads();
        int kn = k0 + 32;
        if (kn < HH) {
            #pragma unroll
            for (int e = 0; e < 4; e++) pA[e] = *reinterpret_cast<const float2*>(A  + aBase + kn + (uint)(16*e)*HH);
            #pragma unroll
            for (int e = 0; e < 8; e++) pB[e] = *reinterpret_cast<const float2*>(PW + bBase + kn + (uint)(16*e)*HH);
        }
        #pragma unroll
        for (int kp = 0; kp < 16; kp++) {
            ulonglong2 b0v = *reinterpret_cast<const ulonglong2*>(&B2s[kp*142 + e0]);
            ulonglong2 b1v = *reinterpret_cast<const ulonglong2*>(&B2s[kp*142 + e1]);
            #pragma unroll
            for (int j = 0; j < 4; j++) {
                ulonglong2 av = *reinterpret_cast<const ulonglong2*>(&A2s[kp*66 + 8*ty + 2*j]);
                fma2(acc[2*j  ][0], av.x, b0v.x); fma2(acc[2*j  ][1], av.x, b0v.y);
                fma2(acc[2*j  ][2], av.x, b1v.x); fma2(acc[2*j  ][3], av.x, b1v.y);
                fma2(acc[2*j+1][0], av.y, b0v.x); fma2(acc[2*j+1][1], av.y, b0v.y);
                fma2(acc[2*j+1][2], av.y, b1v.x); fma2(acc[2*j+1][3], av.y, b1v.y);
            }
        }
    }

    float* lout = out + TT * B_;                 // logits after preds
    int col0 = cb + 4*tx;
    float4 pb = *reinterpret_cast<const float4*>(PB + col0);
    #pragma unroll
    for (int rr = 0; rr < 8; rr++) {
        int b = 8*ty + rr;
        float4 v;
        v.x = foldp(acc[rr][0]) + pb.x;
        v.y = foldp(acc[rr][1]) + pb.y;
        v.z = foldp(acc[rr][2]) + pb.z;
        v.w = foldp(acc[rr][3]) + pb.w;
        *reinterpret_cast<float4*>(lout + ((size_t)b * TT + t) * VV + col0) = v;
        ULL key = mkkey(v.x, col0);
        ULL k2  = mkkey(v.y, col0 + 1); if (k2 > key) key = k2;
        k2      = mkkey(v.z, col0 + 2); if (k2 > key) key = k2;
        k2      = mkkey(v.w, col0 + 3); if (k2 > key) key = k2;
        #pragma unroll
        for (int off = 16; off > 0; off >>= 1) {
            ULL o = __shfl_xor_sync(0xFFFFFFFFu, key, off);
            if (o > key) key = o;
        }
        if (tx == 0) atomicMax(&g_keys[t * B_ + b], key);
    }
}

// ---------------- 6) finalize preds ----------------
__global__ void preds_kernel(float* __restrict__ out) {
    int i = blockIdx.x * 256 + threadIdx.x;
    if (i >= TT * B_) return;
    ULL k = g_keys[i];
    unsigned col = 0xFFFFFFFFu - (unsigned)(k & 0xFFFFFFFFull);
    int t = i >> 6, b = i & 63;
    out[b * TT + t] = (float)col;
}

// ---------------- launch ----------------
extern "C" void kernel_launch(void* const* d_in, const int* in_sizes, int n_in,
                              void* d_out, int out_size) {
    const int*   ids    = (const int*)  d_in[0];
    const float* istate = (const float*)d_in[1];
    const float* emb    = (const float*)d_in[2];
    const float* encW   = (const float*)d_in[3];
    const float* Wih0   = (const float*)d_in[4];
    const float* Whh0   = (const float*)d_in[5];
    const float* bih0   = (const float*)d_in[6];
    const float* bhh0   = (const float*)d_in[7];
    const float* Wih1   = (const float*)d_in[8];
    const float* Whh1   = (const float*)d_in[9];
    const float* bih1   = (const float*)d_in[10];
    const float* bhh1   = (const float*)d_in[11];
    const float* PW     = (const float*)d_in[12];
    const float* PB     = (const float*)d_in[13];
    float* out = (float*)d_out;

    pack_kernel<<<(G4 * 2048) / 256, 256>>>(Wih0, Whh0, Wih1, Whh1, bih0, bhh0, bih1, bhh1);
    h0init_kernel<<<32, 128>>>(istate, encW);
    embx_kernel<<<dim3(TT, 32), 256>>>(ids, emb);
    for (int t = 0; t < TT; t++) {
        cell_kernel<<<128, 256>>>(t, 0);
        cell_kernel<<<128, 256>>>(t, 1);
    }
    proj_kernel<<<dim3(TT, 250), 256>>>(PW, PB, out);
    preds_kernel<<<16, 256>>>(out);
}

// round 16
// speedup vs baseline: 1.7800x; 1.0995x over previous
#include <cuda_runtime.h>
#include <cuda_bf16.h>
#include <math.h>
#include <stdint.h>

typedef unsigned long long ULL;
typedef unsigned int uint;

// ---------------- constants ----------------
#define B_   64
#define TT   63          // time steps actually computed (T-1)
#define EE   512
#define HH   1024
#define VV   32000
#define G4   4096        // 4*H
#define KPK  6144        // 6-term split K for tensor projection
#define NKB  96          // 6144 / 64 k-blocks

// ---------------- scratch (device globals; no allocation) ----------------
__device__ __align__(16) float g_Wih0p[G4 * EE];
__device__ __align__(16) float g_Whh0p[G4 * HH];
__device__ __align__(16) float g_W1cat[G4 * 2 * HH];
__device__ __align__(16) float g_b0p[G4];
__device__ __align__(16) float g_b1p[G4];
__device__ __align__(16) float g_G0x[TT * B_ * G4];
__device__ __align__(16) float g_H1 [TT * B_ * HH];
__device__ __align__(16) float g_h0buf[2][B_ * HH];
__device__ __align__(16) float g_h1buf[2][B_ * HH];
__device__ __align__(16) float g_c0s[B_ * HH];
__device__ __align__(16) float g_c1s[B_ * HH];
__device__ __align__(16) ULL   g_keys[TT * B_];
__device__ __align__(16) __nv_bfloat16 g_Ahat[(size_t)4096 * KPK];    //  50 MB split H1
__device__ __align__(16) __nv_bfloat16 g_Bhat[(size_t)VV   * KPK];    // 393 MB split proj_W

// ---------------- generic helpers ----------------
static __device__ __forceinline__ void fma2(ULL& acc, ULL a, ULL b) {
    asm("fma.rn.f32x2 %0, %1, %2, %0;" : "+l"(acc) : "l"(a), "l"(b));
}
static __device__ __forceinline__ ULL mk2(float x, float y) {
    ULL r;
    asm("mov.b64 %0, {%1, %2};" : "=l"(r)
        : "r"(__float_as_uint(x)), "r"(__float_as_uint(y)));
    return r;
}
static __device__ __forceinline__ float selh(ULL u, int hi) {
    return __uint_as_float(hi ? (unsigned)(u >> 32) : (unsigned)u);
}
static __device__ __forceinline__ float foldp(ULL u) { return selh(u,0) + selh(u,1); }
static __device__ __forceinline__ ULL dup2(float b) {
    ULL r; unsigned u = __float_as_uint(b);
    asm("mov.b64 %0, {%1, %1};" : "=l"(r) : "r"(u));
    return r;
}
static __device__ __forceinline__ float sigf(float x) { return 1.0f / (1.0f + expf(-x)); }
static __device__ __forceinline__ unsigned fordu(float v) {
    unsigned u = __float_as_uint(v);
    return u ^ (((int)u >> 31) | 0x80000000u);
}
static __device__ __forceinline__ ULL mkkey(float v, int col) {
    return ((ULL)fordu(v) << 32) | (ULL)(0xFFFFFFFFu - (unsigned)col);
}
static __device__ __forceinline__ int bcol(int c) { return c + ((c >> 4) << 1); }

// ---------------- sm_80-level tensor helpers (no arch-suffix features) ----------------
static __device__ __forceinline__ uint32_t smem_u32(const void* p) {
    uint32_t a;
    asm("{ .reg .u64 t; cvta.to.shared.u64 t, %1; cvt.u32.u64 %0, t; }" : "=r"(a) : "l"(p));
    return a;
}
static __device__ __forceinline__ void ldsm4(uint32_t* r, uint32_t addr) {
    asm volatile("ldmatrix.sync.aligned.m8n8.x4.shared.b16 {%0,%1,%2,%3}, [%4];"
        : "=r"(r[0]), "=r"(r[1]), "=r"(r[2]), "=r"(r[3]) : "r"(addr));
}
static __device__ __forceinline__ void mma16816(float* c, const uint32_t* a, const uint32_t* b) {
    asm volatile("mma.sync.aligned.m16n8k16.row.col.f32.bf16.bf16.f32 "
        "{%0,%1,%2,%3}, {%4,%5,%6,%7}, {%8,%9}, {%0,%1,%2,%3};"
        : "+f"(c[0]), "+f"(c[1]), "+f"(c[2]), "+f"(c[3])
        : "r"(a[0]), "r"(a[1]), "r"(a[2]), "r"(a[3]), "r"(b[0]), "r"(b[1]));
}
#define CP_ASYNC16(sm, gp) \
    asm volatile("cp.async.cg.shared.global [%0], [%1], 16;" :: "r"(sm), "l"(gp) : "memory")
#define CP_COMMIT() asm volatile("cp.async.commit_group;" ::: "memory")
#define CP_WAIT2()  asm volatile("cp.async.wait_group 2;" ::: "memory")

// ---------------- 1) pack / init ----------------
__global__ void pack_kernel(const float* __restrict__ Wih0, const float* __restrict__ Whh0,
                            const float* __restrict__ Wih1, const float* __restrict__ Whh1,
                            const float* __restrict__ bih0, const float* __restrict__ bhh0,
                            const float* __restrict__ bih1, const float* __restrict__ bhh1) {
    int i = blockIdx.x * 256 + threadIdx.x;
    if (i < TT * B_) g_keys[i] = 0ull;
    int rp  = i >> 11;
    int k   = i & 2047;
    int old = ((rp & 3) << 10) + (rp >> 2);
    g_W1cat[i] = (k < HH) ? Wih1[old * HH + k] : Whh1[old * HH + (k - HH)];
    if (k < EE) g_Wih0p[rp * EE + k] = Wih0[old * EE + k];
    if (k < HH) g_Whh0p[rp * HH + k] = Whh0[old * HH + k];
    if (k == 0) {
        g_b0p[rp] = bih0[old] + bhh0[old];
        g_b1p[rp] = bih1[old] + bhh1[old];
    }
}

// ---------------- 1b) split packers for tensor projection ----------------
__global__ void packB_kernel(const float* __restrict__ PW) {
    int i = blockIdx.x * 256 + threadIdx.x;           // over 32000*1024
    int k = i & 1023;
    float x = PW[i];
    __nv_bfloat16 h = __float2bfloat16(x);
    float fh = __bfloat162float(h);
    __nv_bfloat16 m = __float2bfloat16(x - fh);
    float fm = __bfloat162float(m);
    __nv_bfloat16 l = __float2bfloat16(x - fh - fm);
    size_t base = (size_t)(i >> 10) * KPK + k;
    // B segs: [h, h, m, h, l, m]
    g_Bhat[base         ] = h;
    g_Bhat[base + 1024  ] = h;
    g_Bhat[base + 2048  ] = m;
    g_Bhat[base + 3072  ] = h;
    g_Bhat[base + 4096  ] = l;
    g_Bhat[base + 5120  ] = m;
}
__global__ void packA_kernel() {
    int i = blockIdx.x * 256 + threadIdx.x;           // over 4096*1024
    int r = i >> 10, k = i & 1023;
    float x = (r < TT * B_) ? g_H1[(size_t)r * HH + k] : 0.0f;
    __nv_bfloat16 h = __float2bfloat16(x);
    float fh = __bfloat162float(h);
    __nv_bfloat16 m = __float2bfloat16(x - fh);
    float fm = __bfloat162float(m);
    __nv_bfloat16 l = __float2bfloat16(x - fh - fm);
    size_t base = (size_t)r * KPK + k;
    // A segs: [h, m, h, l, h, m]
    g_Ahat[base         ] = h;
    g_Ahat[base + 1024  ] = m;
    g_Ahat[base + 2048  ] = h;
    g_Ahat[base + 3072  ] = l;
    g_Ahat[base + 4096  ] = h;
    g_Ahat[base + 5120  ] = m;
}

// ---------------- 2) h0 init ----------------
__global__ __launch_bounds__(128) void h0init_kernel(const float* __restrict__ S,
                                                     const float* __restrict__ EW) {
    __shared__ float A_sm[32 * 66];
    __shared__ float B_sm[32 * 36];
    int tid = threadIdx.x, tr = tid >> 3, tc = tid & 7;
    int cb = blockIdx.x * 32;
    ULL acc[2][4] = {{0,0,0,0},{0,0,0,0}};
    float pA[16], pB[8];
    #pragma unroll
    for (int e = 0; e < 16; e++) { int idx = e*128+tid; pA[e] = S[(idx>>5)*2048 + (idx&31)]; }
    #pragma unroll
    for (int e = 0; e < 8;  e++) { int idx = e*128+tid; pB[e] = EW[(size_t)(cb+(idx>>5))*2048 + (idx&31)]; }
    for (int k0 = 0; k0 < 2048; k0 += 32) {
        __syncthreads();
        #pragma unroll
        for (int e = 0; e < 16; e++) { int idx = e*128+tid; A_sm[(idx&31)*66 + (idx>>5)] = pA[e]; }
        #pragma unroll
        for (int e = 0; e < 8;  e++) { int idx = e*128+tid; B_sm[(idx&31)*36 + (idx>>5)] = pB[e]; }
        __syncthreads();
        int kn = k0 + 32;
        if (kn < 2048) {
            #pragma unroll
            for (int e = 0; e < 16; e++) { int idx = e*128+tid; pA[e] = S[(idx>>5)*2048 + kn + (idx&31)]; }
            #pragma unroll
            for (int e = 0; e < 8;  e++) { int idx = e*128+tid; pB[e] = EW[(size_t)(cb+(idx>>5))*2048 + kn + (idx&31)]; }
        }
        #pragma unroll 8
        for (int kk = 0; kk < 32; kk++) {
            const ULL* ar = reinterpret_cast<const ULL*>(A_sm + kk * 66);
            ULL a0 = ar[2*tr], a1 = ar[2*tr+1];
            float4 bv = *reinterpret_cast<const float4*>(B_sm + kk*36 + 4*tc);
            ULL b0 = dup2(bv.x), b1 = dup2(bv.y), b2 = dup2(bv.z), b3 = dup2(bv.w);
            fma2(acc[0][0], a0, b0); fma2(acc[1][0], a1, b0);
            fma2(acc[0][1], a0, b1); fma2(acc[1][1], a1, b1);
            fma2(acc[0][2], a0, b2); fma2(acc[1][2], a1, b2);
            fma2(acc[0][3], a0, b3); fma2(acc[1][3], a1, b3);
        }
    }
    #pragma unroll
    for (int p = 0; p < 2; p++)
        #pragma unroll
        for (int hi = 0; hi < 2; hi++) {
            int r = 4*tr + 2*p + hi;
            #pragma unroll
            for (int c = 0; c < 4; c++) {
                int col = cb + 4*tc + c;
                float v = selh(acc[p][c], hi);
                g_h0buf[0][r*HH + col] = v;
                g_c0s   [r*HH + col]   = v;
                g_h1buf[0][r*HH + col] = v;
                g_c1s   [r*HH + col]   = v;
            }
        }
}

// ---------------- 3) embx (R8, measured good) ----------------
__global__ __launch_bounds__(256, 2) void embx_kernel(const int* __restrict__ ids,
                                                      const float* __restrict__ emb) {
    __shared__ ULL A2s[16 * 66];
    __shared__ ULL B2s[16 * 142];
    __shared__ int ids_sm[B_];
    int tid = threadIdx.x, ty = tid >> 5, tx = tid & 31;
    int t = blockIdx.x, cb = blockIdx.y * 128;
    if (tid < B_) ids_sm[tid] = ids[tid * 64 + t];
    __syncthreads();
    ULL acc[8][4];
    #pragma unroll
    for (int r = 0; r < 8; r++)
        #pragma unroll
        for (int c = 0; c < 4; c++) acc[r][c] = 0ull;
    int kp_l = tid & 15, lr = tid >> 4;
    uint aG[4];
    #pragma unroll
    for (int e = 0; e < 4; e++) aG[e] = (uint)ids_sm[lr + 16*e] * EE + 2*kp_l;
    uint bG = (uint)(cb + lr) * EE + 2*kp_l;
    int aS = kp_l*66 + lr;
    int bSb = kp_l*142;
    int bE[8];
    #pragma unroll
    for (int e = 0; e < 8; e++) bE[e] = bcol(lr + 16*e);
    int e0 = bcol(4*tx), e1 = bcol(4*tx + 2);
    float2 pA[4], pB[8];
    #pragma unroll
    for (int e = 0; e < 4; e++) pA[e] = *reinterpret_cast<const float2*>(emb + aG[e]);
    #pragma unroll
    for (int e = 0; e < 8; e++) pB[e] = *reinterpret_cast<const float2*>(g_Wih0p + bG + (uint)(16*e)*EE);
    for (int k0 = 0; k0 < EE; k0 += 32) {
        __syncthreads();
        #pragma unroll
        for (int e = 0; e < 4; e++) A2s[aS + 16*e]  = *reinterpret_cast<ULL*>(&pA[e]);
        #pragma unroll
        for (int e = 0; e < 8; e++) B2s[bSb + bE[e]] = *reinterpret_cast<ULL*>(&pB[e]);
        __syncthreads();
        int kn = k0 + 32;
        if (kn < EE) {
            #pragma unroll
            for (int e = 0; e < 4; e++) pA[e] = *reinterpret_cast<const float2*>(emb + aG[e] + kn);
            #pragma unroll
            for (int e = 0; e < 8; e++) pB[e] = *reinterpret_cast<const float2*>(g_Wih0p + bG + kn + (uint)(16*e)*EE);
        }
        #pragma unroll
        for (int kp = 0; kp < 16; kp++) {
            ulonglong2 b0v = *reinterpret_cast<const ulonglong2*>(&B2s[kp*142 + e0]);
            ulonglong2 b1v = *reinterpret_cast<const ulonglong2*>(&B2s[kp*142 + e1]);
            #pragma unroll
            for (int j = 0; j < 4; j++) {
                ulonglong2 av = *reinterpret_cast<const ulonglong2*>(&A2s[kp*66 + 8*ty + 2*j]);
                fma2(acc[2*j  ][0], av.x, b0v.x); fma2(acc[2*j  ][1], av.x, b0v.y);
                fma2(acc[2*j  ][2], av.x, b1v.x); fma2(acc[2*j  ][3], av.x, b1v.y);
                fma2(acc[2*j+1][0], av.y, b0v.x); fma2(acc[2*j+1][1], av.y, b0v.y);
                fma2(acc[2*j+1][2], av.y, b1v.x); fma2(acc[2*j+1][3], av.y, b1v.y);
            }
        }
    }
    float* outp = g_G0x + (size_t)(t * B_) * G4;
    int col0 = cb + 4*tx;
    float4 bb = *reinterpret_cast<const float4*>(g_b0p + col0);
    #pragma unroll
    for (int rr = 0; rr < 8; rr++) {
        int row = 8*ty + rr;
        float4 v;
        v.x = foldp(acc[rr][0]) + bb.x;
        v.y = foldp(acc[rr][1]) + bb.y;
        v.z = foldp(acc[rr][2]) + bb.z;
        v.w = foldp(acc[rr][3]) + bb.w;
        *reinterpret_cast<float4*>(outp + (size_t)row*G4 + col0) = v;
    }
}

// ---------------- 4) fused LSTM cell (R8, measured good) ----------------
__global__ __launch_bounds__(256) void cell_kernel(int t, int layer) {
    __shared__ ULL A2b[2][16 * 66];
    __shared__ ULL B2b[2][16 * 34];
    int tid = threadIdx.x;
    int w = tid >> 5, l = tid & 31;
    int r0 = 8*w + 2*(l >> 3);
    int cg = l & 7;
    int cb = blockIdx.x * 32;
    int in = t & 1, out = in ^ 1;
    const float *A1, *A2g, *W;
    float *cst, *hout, *hcopy = nullptr;
    int K;
    if (layer == 0) {
        A1 = g_h0buf[in]; A2g = A1; W = g_Whh0p; K = HH;
        cst = g_c0s; hout = g_h0buf[out];
    } else {
        A1 = g_h0buf[out]; A2g = g_h1buf[in]; W = g_W1cat; K = 2 * HH;
        cst = g_c1s; hout = g_h1buf[out];
        hcopy = g_H1 + (size_t)(t * B_) * HH;
    }
    int gc0 = cb + 4*cg;
    ULL acc[2][4];
    if (layer == 0) {
        const float* initp = g_G0x + (size_t)(t * B_) * G4;
        float4 i0 = *reinterpret_cast<const float4*>(initp + (size_t)r0     * G4 + gc0);
        float4 i1 = *reinterpret_cast<const float4*>(initp + (size_t)(r0+1) * G4 + gc0);
        acc[0][0] = mk2(i0.x, 0.f); acc[0][1] = mk2(i0.y, 0.f);
        acc[0][2] = mk2(i0.z, 0.f); acc[0][3] = mk2(i0.w, 0.f);
        acc[1][0] = mk2(i1.x, 0.f); acc[1][1] = mk2(i1.y, 0.f);
        acc[1][2] = mk2(i1.z, 0.f); acc[1][3] = mk2(i1.w, 0.f);
    } else {
        float4 bb = *reinterpret_cast<const float4*>(g_b1p + gc0);
        acc[0][0] = mk2(bb.x, 0.f); acc[0][1] = mk2(bb.y, 0.f);
        acc[0][2] = mk2(bb.z, 0.f); acc[0][3] = mk2(bb.w, 0.f);
        acc[1][0] = acc[0][0]; acc[1][1] = acc[0][1];
        acc[1][2] = acc[0][2]; acc[1][3] = acc[0][3];
    }
    int kp_l = l & 15, half = l >> 4;
    int rowA = 2*w + half;
    int colB = w + 8*half;
    uint aBase = (uint)rowA * HH + 2*kp_l;
    uint bBase = (uint)(cb + colB) * K + 2*kp_l;
    int aS = kp_l*66 + rowA;
    int bS0 = kp_l*34 + colB;
    int bS1 = kp_l*34 + colB + 18;
    int e0 = 4*cg + ((cg >= 4) ? 2 : 0);
    int e1 = e0 + 2;
    int nb = K >> 5;
    float2 pA[4], pB[2];
    #pragma unroll
    for (int e = 0; e < 4; e++) pA[e] = *reinterpret_cast<const float2*>(A1 + aBase + (uint)(16*e)*HH);
    pB[0] = *reinterpret_cast<const float2*>(W + bBase);
    pB[1] = *reinterpret_cast<const float2*>(W + bBase + (uint)16*K);
    #pragma unroll
    for (int e = 0; e < 4; e++) A2b[0][aS + 16*e] = *reinterpret_cast<ULL*>(&pA[e]);
    B2b[0][bS0] = *reinterpret_cast<ULL*>(&pB[0]);
    B2b[0][bS1] = *reinterpret_cast<ULL*>(&pB[1]);
    if (nb > 1) {
        #pragma unroll
        for (int e = 0; e < 4; e++) pA[e] = *reinterpret_cast<const float2*>(A1 + 32 + aBase + (uint)(16*e)*HH);
        pB[0] = *reinterpret_cast<const float2*>(W + bBase + 32);
        pB[1] = *reinterpret_cast<const float2*>(W + bBase + 32 + (uint)16*K);
    }
    for (int blk = 0; blk < nb; blk++) {
        __syncthreads();
        int cur = blk & 1, nxt = cur ^ 1;
        if (blk + 1 < nb) {
            #pragma unroll
            for (int e = 0; e < 4; e++) A2b[nxt][aS + 16*e] = *reinterpret_cast<ULL*>(&pA[e]);
            B2b[nxt][bS0] = *reinterpret_cast<ULL*>(&pB[0]);
            B2b[nxt][bS1] = *reinterpret_cast<ULL*>(&pB[1]);
            if (blk + 2 < nb) {
                int k0 = (blk + 2) << 5;
                const float* Asrc = (k0 < HH) ? (A1 + k0) : (A2g + (k0 - HH));
                #pragma unroll
                for (int e = 0; e < 4; e++) pA[e] = *reinterpret_cast<const float2*>(Asrc + aBase + (uint)(16*e)*HH);
                pB[0] = *reinterpret_cast<const float2*>(W + bBase + k0);
                pB[1] = *reinterpret_cast<const float2*>(W + bBase + k0 + (uint)16*K);
            }
        }
        const ULL* Ab = A2b[cur];
        const ULL* Bb = B2b[cur];
        #pragma unroll
        for (int kp = 0; kp < 16; kp++) {
            ulonglong2 av  = *reinterpret_cast<const ulonglong2*>(&Ab[kp*66 + r0]);
            ulonglong2 b0v = *reinterpret_cast<const ulonglong2*>(&Bb[kp*34 + e0]);
            ulonglong2 b1v = *reinterpret_cast<const ulonglong2*>(&Bb[kp*34 + e1]);
            fma2(acc[0][0], av.x, b0v.x); fma2(acc[0][1], av.x, b0v.y);
            fma2(acc[0][2], av.x, b1v.x); fma2(acc[0][3], av.x, b1v.y);
            fma2(acc[1][0], av.y, b0v.x); fma2(acc[1][1], av.y, b0v.y);
            fma2(acc[1][2], av.y, b1v.x); fma2(acc[1][3], av.y, b1v.y);
        }
    }
    int j = (cb >> 2) + cg;
    #pragma unroll
    for (int r = 0; r < 2; r++) {
        int row = r0 + r;
        float iv = foldp(acc[r][0]);
        float fv = foldp(acc[r][1]);
        float gv = foldp(acc[r][2]);
        float ov = foldp(acc[r][3]);
        float cold = cst[row*HH + j];
        float cn = sigf(fv) * cold + sigf(iv) * tanhf(gv);
        float h  = sigf(ov) * tanhf(cn);
        cst [row*HH + j] = cn;
        hout[row*HH + j] = h;
        if (hcopy) hcopy[row*HH + j] = h;
    }
}

// ---------------- 5) HMMA projection: C = Ahat @ Bhat^T (+bias), fused argmax ----
// CTA 128(M)x128(N), 256 thr, warps 2x4 (warp tile 64x32), K-block 64, 3-stage cp.async
// smem: bias @0 (512B), A stage s @ 1024+s*16384, B stage s @ 50176+s*16384 => 99328 B
#define PROJ_SMEM 99328
__global__ __launch_bounds__(256) void proj_mma_kernel(const float* __restrict__ PB,
                                                       float* __restrict__ out) {
    extern __shared__ char smp[];
    uint32_t sbase = smem_u32(smp);
    float* bias_sm = (float*)smp;
    int tid = threadIdx.x;
    int wid = tid >> 5, l = tid & 31;
    int wm = wid >> 2, wn = wid & 3;     // warp grid 2(M) x 4(N)
    int m = blockIdx.x, nt = blockIdx.y;

    if (tid < 32) *(float4*)(bias_sm + 4*tid) = *(const float4*)(PB + nt*128 + 4*tid);

    // ---- fill-role precompute: 4 chunks each for A and B ----
    int fc = tid & 7;                    // 16B chunk in row (0..7)
    const char* aGp[4]; const char* bGp[4];
    uint32_t aSo[4], bSo[4];
    #pragma unroll
    for (int e = 0; e < 4; e++) {
        int row = e*32 + (tid >> 3);
        aGp[e] = (const char*)g_Ahat + 2*((size_t)(m*128  + row)*KPK + fc*8);
        bGp[e] = (const char*)g_Bhat + 2*((size_t)(nt*128 + row)*KPK + fc*8);
        uint32_t so = (uint32_t)(row*128 + ((fc ^ (row & 7)) << 4));
        aSo[e] = sbase + 1024  + so;     // + stage*16384
        bSo[e] = sbase + 50176 + so;     // + stage*16384
    }

#define PROJ_FILL(stage, kbv) do { \
    uint32_t s16_ = (uint32_t)(stage) * 16384u; \
    size_t ko_ = (size_t)(kbv) * 128; \
    _Pragma("unroll") for (int e_ = 0; e_ < 4; e_++) CP_ASYNC16(aSo[e_] + s16_, aGp[e_] + ko_); \
    _Pragma("unroll") for (int e_ = 0; e_ < 4; e_++) CP_ASYNC16(bSo[e_] + s16_, bGp[e_] + ko_); \
} while(0)

    // ---- compute-role precompute ----
    int hi = l >> 4;                     // ldmatrix chunk-half
    uint32_t aRow[4], aXor[4];
    #pragma unroll
    for (int mt = 0; mt < 4; mt++) {
        int row = wm*64 + mt*16 + (l & 15);
        aRow[mt] = sbase + 1024 + (uint32_t)(row*128);
        aXor[mt] = (uint32_t)(row & 7);
    }
    uint32_t bRow[2], bXor[2];
    #pragma unroll
    for (int ng = 0; ng < 2; ng++) {
        int row = wn*32 + ng*16 + (l & 15);
        bRow[ng] = sbase + 50176 + (uint32_t)(row*128);
        bXor[ng] = (uint32_t)(row & 7);
    }

    float acc[4][4][4];
    #pragma unroll
    for (int mt = 0; mt < 4; mt++)
        #pragma unroll
        for (int n8 = 0; n8 < 4; n8++)
            #pragma unroll
            for (int q = 0; q < 4; q++) acc[mt][n8][q] = 0.0f;

    // ---- prologue: 3 stages in flight ----
    PROJ_FILL(0, 0); CP_COMMIT();
    PROJ_FILL(1, 1); CP_COMMIT();
    PROJ_FILL(2, 2); CP_COMMIT();

    #pragma unroll 1
    for (int kb = 0; kb < NKB; kb++) {
        int s = kb % 3;
        uint32_t s16 = (uint32_t)s * 16384u;
        CP_WAIT2();
        __syncthreads();
        #pragma unroll
        for (int kk = 0; kk < 4; kk++) {
            uint32_t a[4][4], b[2][4];
            #pragma unroll
            for (int mt = 0; mt < 4; mt++)
                ldsm4(a[mt], aRow[mt] + s16 + (((uint32_t)(kk*2 + hi) ^ aXor[mt]) << 4));
            #pragma unroll
            for (int ng = 0; ng < 2; ng++)
                ldsm4(b[ng], bRow[ng] + s16 + (((uint32_t)(kk*2 + hi) ^ bXor[ng]) << 4));
            #pragma unroll
            for (int mt = 0; mt < 4; mt++) {
                #pragma unroll
                for (int n8 = 0; n8 < 4; n8++) {
                    uint32_t bb[2] = { b[n8 >> 1][(n8 & 1)], b[n8 >> 1][(n8 & 1) + 2] };
                    mma16816(acc[mt][n8], a[mt], bb);
                }
            }
        }
        __syncthreads();
        if (kb + 3 < NKB) PROJ_FILL(s, kb + 3);
        CP_COMMIT();
    }

    // ---- epilogue: bias + logits + fused argmax keys ----
    float* lout = out + TT * B_;
    int cloc = wn*32 + (l & 3)*2;        // local col base (within 128)
    #pragma unroll
    for (int mt = 0; mt < 4; mt++) {
        #pragma unroll
        for (int h = 0; h < 2; h++) {
            int grow = m*128 + wm*64 + mt*16 + (l >> 2) + 8*h;
            if (grow < TT * B_) {
                int tt = grow >> 6, bb_ = grow & 63;
                float* rowp = lout + ((size_t)bb_ * TT + tt) * VV + nt*128;
                ULL key = 0ull;
                #pragma unroll
                for (int n8 = 0; n8 < 4; n8++) {
                    int lc = cloc + n8*8;
                    float v0 = acc[mt][n8][2*h]   + bias_sm[lc];
                    float v1 = acc[mt][n8][2*h+1] + bias_sm[lc+1];
                    float2 vv; vv.x = v0; vv.y = v1;
                    *(float2*)(rowp + lc) = vv;
                    int gc = nt*128 + lc;
                    ULL k1 = mkkey(v0, gc);
                    ULL k2 = mkkey(v1, gc + 1); if (k2 > k1) k1 = k2;
                    if (k1 > key) key = k1;
                }
                ULL o = __shfl_xor_sync(0xFFFFFFFFu, key, 1); if (o > key) key = o;
                o     = __shfl_xor_sync(0xFFFFFFFFu, key, 2); if (o > key) key = o;
                if ((l & 3) == 0) atomicMax(&g_keys[tt * B_ + bb_], key);
            }
        }
    }
}

// ---------------- 6) finalize preds ----------------
__global__ void preds_kernel(float* __restrict__ out) {
    int i = blockIdx.x * 256 + threadIdx.x;
    if (i >= TT * B_) return;
    ULL k = g_keys[i];
    unsigned col = 0xFFFFFFFFu - (unsigned)(k & 0xFFFFFFFFull);
    int t = i >> 6, b = i & 63;
    out[b * TT + t] = (float)col;
}

// ---------------- launch ----------------
extern "C" void kernel_launch(void* const* d_in, const int* in_sizes, int n_in,
                              void* d_out, int out_size) {
    const int*   ids    = (const int*)  d_in[0];
    const float* istate = (const float*)d_in[1];
    const float* emb    = (const float*)d_in[2];
    const float* encW   = (const float*)d_in[3];
    const float* Wih0   = (const float*)d_in[4];
    const float* Whh0   = (const float*)d_in[5];
    const float* bih0   = (const float*)d_in[6];
    const float* bhh0   = (const float*)d_in[7];
    const float* Wih1   = (const float*)d_in[8];
    const float* Whh1   = (const float*)d_in[9];
    const float* bih1   = (const float*)d_in[10];
    const float* bhh1   = (const float*)d_in[11];
    const float* PW     = (const float*)d_in[12];
    const float* PB     = (const float*)d_in[13];
    float* out = (float*)d_out;

    cudaFuncSetAttribute(proj_mma_kernel, cudaFuncAttributeMaxDynamicSharedMemorySize, PROJ_SMEM);

    pack_kernel<<<(G4 * 2048) / 256, 256>>>(Wih0, Whh0, Wih1, Whh1, bih0, bhh0, bih1, bhh1);
    packB_kernel<<<(VV * 1024) / 256, 256>>>(PW);
    h0init_kernel<<<32, 128>>>(istate, encW);
    embx_kernel<<<dim3(TT, 32), 256>>>(ids, emb);
    for (int t = 0; t < TT; t++) {
        cell_kernel<<<128, 256>>>(t, 0);
        cell_kernel<<<128, 256>>>(t, 1);
    }
    packA_kernel<<<(4096 * 1024) / 256, 256>>>();
    proj_mma_kernel<<<dim3(32, 250), 256, PROJ_SMEM>>>(PB, out);
    preds_kernel<<<16, 256>>>(out);
}